// round 1
// baseline (speedup 1.0000x reference)
#include <cuda_runtime.h>
#include <math.h>

#define H_    8
#define D_    64
#define HID_  256
#define T_    2048
#define S_    2048
#define B_    4
#define NROW_ (T_*B_)

// Scratch (allocation-free): q/k/v projections in [b*H+h][t][d] layout,
// attention context in [t*B+b][h*D+d] layout.
__device__ float g_q[B_*H_*T_*D_];
__device__ float g_k[B_*H_*S_*D_];
__device__ float g_v[B_*H_*S_*D_];
__device__ float g_ctx[NROW_*H_*D_];

// ---------------------------------------------------------------------------
// Fused 2-layer MLP projection: out = relu(x@W1+b1)@W2+b2, scaled, scattered
// into [b][h][t][d] layout. 16 rows per block, 256 threads.
// ---------------------------------------------------------------------------
__global__ void __launch_bounds__(256) mlp_kernel(
    const float* __restrict__ x,
    const float* __restrict__ W1, const float* __restrict__ b1,
    const float* __restrict__ W2, const float* __restrict__ b2,
    int which, float scale)
{
    float* out = (which == 0) ? g_q : (which == 1) ? g_k : g_v;
    __shared__ float Xs[16][64];
    __shared__ float Hs[16][HID_];
    const int n0 = blockIdx.x * 16;
    const int t  = threadIdx.x;

    // load X tile [16][64]
    for (int i = t; i < 16 * 16; i += 256) {
        int r = i >> 4, c4 = (i & 15) * 4;
        float4 v = *(const float4*)(x + (size_t)(n0 + r) * 64 + c4);
        Xs[r][c4+0] = v.x; Xs[r][c4+1] = v.y; Xs[r][c4+2] = v.z; Xs[r][c4+3] = v.w;
    }
    __syncthreads();

    // layer 1: each thread owns hidden column j = t for all 16 rows
    float acc[16];
    {
        float bv = b1[t];
        #pragma unroll
        for (int r = 0; r < 16; r++) acc[r] = bv;
    }
    #pragma unroll 4
    for (int k = 0; k < 64; k++) {
        float w = W1[k * HID_ + t];
        #pragma unroll
        for (int r = 0; r < 16; r++) acc[r] += Xs[r][k] * w;
    }
    #pragma unroll
    for (int r = 0; r < 16; r++) Hs[r][t] = fmaxf(acc[r], 0.0f);
    __syncthreads();

    // layer 2: each thread owns output columns t and t+256 for all 16 rows
    float a0[16], a1[16];
    {
        float bv0 = b2[t], bv1 = b2[t + 256];
        #pragma unroll
        for (int r = 0; r < 16; r++) { a0[r] = bv0; a1[r] = bv1; }
    }
    #pragma unroll 2
    for (int k = 0; k < HID_; k++) {
        float w0 = W2[k * 512 + t];
        float w1 = W2[k * 512 + t + 256];
        #pragma unroll
        for (int r = 0; r < 16; r++) {
            float hh = Hs[r][k];
            a0[r] += hh * w0;
            a1[r] += hh * w1;
        }
    }
    const int j0 = t, j1 = t + 256;
    const int h0 = j0 >> 6, d0 = j0 & 63;
    const int h1 = j1 >> 6, d1 = j1 & 63;
    #pragma unroll
    for (int r = 0; r < 16; r++) {
        int n  = n0 + r;
        int tt = n >> 2;      // n / B_
        int bb = n & 3;       // n % B_
        out[((size_t)(bb * H_ + h0) * T_ + tt) * D_ + d0] = a0[r] * scale;
        out[((size_t)(bb * H_ + h1) * T_ + tt) * D_ + d1] = a1[r] * scale;
    }
}

// ---------------------------------------------------------------------------
// Flash attention, fp32, online softmax with additive mask.
// BM=128 query rows/block, BN=64 keys/tile, 256 threads, 8x4 register tile.
// Smem rows padded to 65 floats -> conflict-free (65 == 1 mod 32).
// ---------------------------------------------------------------------------
#define BM   128
#define BN   64
#define PADW 65

__global__ void __launch_bounds__(256, 2) flash_kernel(const float* __restrict__ mask)
{
    extern __shared__ float smf[];
    float* Qs   = smf;                   // BM*PADW
    float* Ks   = Qs + BM * PADW;        // BN*PADW
    float* Vs   = Ks + BN * PADW;        // BN*PADW
    float* Ps   = Vs + BN * PADW;        // BM*PADW: mask -> scores -> probs
    float* mrow = Ps + BM * PADW;        // BM
    float* lrow = mrow + BM;             // BM
    float* arow = lrow + BM;             // BM

    const int tb  = blockIdx.x, bh = blockIdx.y;
    const int b   = bh >> 3, h = bh & 7;
    const int t0  = tb * BM;
    const int tid = threadIdx.x;
    const int rg  = tid >> 4;            // 0..15: rows rg*8 .. rg*8+7
    const int cg  = tid & 15;            // 0..15: cols cg, cg+16, cg+32, cg+48

    const float* qp = g_q + (size_t)bh * T_ * D_ + (size_t)t0 * D_;
    const float* kp = g_k + (size_t)bh * S_ * D_;
    const float* vp = g_v + (size_t)bh * S_ * D_;
    const float* mp = mask + (size_t)b * T_ * S_ + (size_t)t0 * S_;

    // load Q tile [BM][64]
    for (int i = tid; i < BM * 16; i += 256) {
        int r = i >> 4, c4 = (i & 15) * 4;
        float4 v = *(const float4*)(qp + (size_t)r * D_ + c4);
        float* q = Qs + r * PADW + c4;
        q[0] = v.x; q[1] = v.y; q[2] = v.z; q[3] = v.w;
    }
    if (tid < BM) { mrow[tid] = -3.0e38f; lrow[tid] = 0.0f; }

    float O[8][4];
    #pragma unroll
    for (int i = 0; i < 8; i++)
        #pragma unroll
        for (int j = 0; j < 4; j++) O[i][j] = 0.0f;

    for (int s0 = 0; s0 < S_; s0 += BN) {
        __syncthreads();   // protect smem from overwrite while prior PV reads run
        // K, V tiles [BN][64]
        for (int i = tid; i < BN * 16; i += 256) {
            int r = i >> 4, c4 = (i & 15) * 4;
            float4 kv = *(const float4*)(kp + (size_t)(s0 + r) * D_ + c4);
            float4 vv = *(const float4*)(vp + (size_t)(s0 + r) * D_ + c4);
            float* kd = Ks + r * PADW + c4;
            kd[0] = kv.x; kd[1] = kv.y; kd[2] = kv.z; kd[3] = kv.w;
            float* vd = Vs + r * PADW + c4;
            vd[0] = vv.x; vd[1] = vv.y; vd[2] = vv.z; vd[3] = vv.w;
        }
        // mask tile [BM][BN] -> Ps (scores accumulate onto it)
        for (int i = tid; i < BM * (BN / 4); i += 256) {
            int r = i >> 4, c4 = (i & 15) * 4;
            float4 mv = *(const float4*)(mp + (size_t)r * S_ + s0 + c4);
            float* pd = Ps + r * PADW + c4;
            pd[0] = mv.x; pd[1] = mv.y; pd[2] = mv.z; pd[3] = mv.w;
        }
        __syncthreads();

        // phase 1: S = Q K^T (+mask already in Ps)
        float s[8][4];
        #pragma unroll
        for (int i = 0; i < 8; i++)
            #pragma unroll
            for (int j = 0; j < 4; j++) s[i][j] = 0.0f;
        #pragma unroll 4
        for (int k = 0; k < D_; k++) {
            float q[8], kk[4];
            #pragma unroll
            for (int i = 0; i < 8; i++) q[i] = Qs[(rg * 8 + i) * PADW + k];
            #pragma unroll
            for (int j = 0; j < 4; j++) kk[j] = Ks[(cg + 16 * j) * PADW + k];
            #pragma unroll
            for (int i = 0; i < 8; i++)
                #pragma unroll
                for (int j = 0; j < 4; j++) s[i][j] += q[i] * kk[j];
        }
        #pragma unroll
        for (int i = 0; i < 8; i++) {
            int r = rg * 8 + i;
            #pragma unroll
            for (int j = 0; j < 4; j++)
                Ps[r * PADW + cg + 16 * j] += s[i][j];
        }
        __syncthreads();

        // phase 2: per-row online softmax (threads 0..127, one row each)
        if (tid < BM) {
            const int r = tid;
            float mold = mrow[r];
            float mx   = mold;
            #pragma unroll 8
            for (int j = 0; j < BN; j++) mx = fmaxf(mx, Ps[r * PADW + j]);
            float ladd = 0.0f;
            #pragma unroll 8
            for (int j = 0; j < BN; j++) {
                float p = __expf(Ps[r * PADW + j] - mx);
                Ps[r * PADW + j] = p;
                ladd += p;
            }
            float al = __expf(mold - mx);
            lrow[r] = lrow[r] * al + ladd;
            mrow[r] = mx;
            arow[r] = al;
        }
        __syncthreads();

        // phase 3: rescale O, accumulate P V
        float alv[8];
        #pragma unroll
        for (int i = 0; i < 8; i++) alv[i] = arow[rg * 8 + i];
        #pragma unroll
        for (int i = 0; i < 8; i++)
            #pragma unroll
            for (int j = 0; j < 4; j++) O[i][j] *= alv[i];

        #pragma unroll 4
        for (int kk2 = 0; kk2 < BN; kk2++) {
            float vv[4];
            #pragma unroll
            for (int j = 0; j < 4; j++) vv[j] = Vs[kk2 * PADW + cg + 16 * j];
            #pragma unroll
            for (int i = 0; i < 8; i++) {
                float p = Ps[(rg * 8 + i) * PADW + kk2];
                #pragma unroll
                for (int j = 0; j < 4; j++) O[i][j] += p * vv[j];
            }
        }
    }

    // epilogue: normalize, scatter to ctx[(t*B+b)][h*64+c]
    #pragma unroll
    for (int i = 0; i < 8; i++) {
        int r = rg * 8 + i;
        float linv = 1.0f / lrow[r];
        size_t row = (size_t)(t0 + r) * B_ + b;
        #pragma unroll
        for (int j = 0; j < 4; j++)
            g_ctx[row * (H_ * D_) + h * D_ + cg + 16 * j] = O[i][j] * linv;
    }
}

// ---------------------------------------------------------------------------
// Output projection: out[8192,64] = ctx[8192,512] @ Wo[512,64] + bo
// ---------------------------------------------------------------------------
__global__ void __launch_bounds__(256) outproj_kernel(
    const float* __restrict__ Wo, const float* __restrict__ bo,
    float* __restrict__ out)
{
    const int n0 = blockIdx.x * 32;
    const int j  = threadIdx.x & 63;
    const int rg = threadIdx.x >> 6;   // 0..3 -> rows rg*8..rg*8+7
    float acc[8];
    {
        float bv = bo[j];
        #pragma unroll
        for (int i = 0; i < 8; i++) acc[i] = bv;
    }
    for (int k = 0; k < 512; k += 4) {
        float w0 = Wo[(k + 0) * 64 + j];
        float w1 = Wo[(k + 1) * 64 + j];
        float w2 = Wo[(k + 2) * 64 + j];
        float w3 = Wo[(k + 3) * 64 + j];
        #pragma unroll
        for (int i = 0; i < 8; i++) {
            const float4 cv = *(const float4*)(g_ctx + (size_t)(n0 + rg * 8 + i) * 512 + k);
            acc[i] += cv.x * w0 + cv.y * w1 + cv.z * w2 + cv.w * w3;
        }
    }
    #pragma unroll
    for (int i = 0; i < 8; i++)
        out[(size_t)(n0 + rg * 8 + i) * 64 + j] = acc[i];
}

// ---------------------------------------------------------------------------
extern "C" void kernel_launch(void* const* d_in, const int* in_sizes, int n_in,
                              void* d_out, int out_size)
{
    const float* query = (const float*)d_in[0];
    const float* key   = (const float*)d_in[1];
    const float* value = (const float*)d_in[2];
    const float* mask  = (const float*)d_in[3];
    const float* Wq1 = (const float*)d_in[4];
    const float* bq1 = (const float*)d_in[5];
    const float* Wq2 = (const float*)d_in[6];
    const float* bq2 = (const float*)d_in[7];
    const float* Wk1 = (const float*)d_in[8];
    const float* bk1 = (const float*)d_in[9];
    const float* Wk2 = (const float*)d_in[10];
    const float* bk2 = (const float*)d_in[11];
    const float* Wv1 = (const float*)d_in[12];
    const float* bv1 = (const float*)d_in[13];
    const float* Wv2 = (const float*)d_in[14];
    const float* bv2 = (const float*)d_in[15];
    const float* Wo  = (const float*)d_in[16];
    const float* bo  = (const float*)d_in[17];
    float* out = (float*)d_out;

    const float scaling = 0.125f;   // DQ^-0.5

    dim3 mlpGrid(NROW_ / 16);
    mlp_kernel<<<mlpGrid, 256>>>(query, Wq1, bq1, Wq2, bq2, 0, scaling);
    mlp_kernel<<<mlpGrid, 256>>>(key,   Wk1, bk1, Wk2, bk2, 1, 1.0f);
    mlp_kernel<<<mlpGrid, 256>>>(value, Wv1, bv1, Wv2, bv2, 2, 1.0f);

    size_t smem = (size_t)(2 * BM * PADW + 2 * BN * PADW + 3 * BM) * sizeof(float);
    cudaFuncSetAttribute(flash_kernel, cudaFuncAttributeMaxDynamicSharedMemorySize, (int)smem);
    dim3 fGrid(T_ / BM, B_ * H_);
    flash_kernel<<<fGrid, 256, smem>>>(mask);

    outproj_kernel<<<NROW_ / 32, 256>>>(Wo, bo, out);
}

// round 2
// speedup vs baseline: 1.8052x; 1.8052x over previous
#include <cuda_runtime.h>
#include <math.h>
#include <stdint.h>

#define H_    8
#define D_    64
#define HID_  256
#define T_    2048
#define S_    2048
#define B_    4
#define NROW_ (T_*B_)

// Scratch (allocation-free)
__device__ float g_q[B_*H_*T_*D_];
__device__ float g_k[B_*H_*S_*D_];
__device__ float g_v[B_*H_*S_*D_];
__device__ float g_ctx[NROW_*H_*D_];

__device__ __forceinline__ float to_tf32(float x) {
    float r;
    asm("cvt.rna.tf32.f32 %0, %1;" : "=f"(r) : "f"(x));
    return r;
}
__device__ __forceinline__ uint32_t fu(float x) { return __float_as_uint(x); }

__device__ __forceinline__ void mma_tf32(float* d,
    uint32_t a0, uint32_t a1, uint32_t a2, uint32_t a3,
    uint32_t b0, uint32_t b1)
{
    asm volatile(
        "mma.sync.aligned.m16n8k8.row.col.f32.tf32.tf32.f32 "
        "{%0,%1,%2,%3}, {%4,%5,%6,%7}, {%8,%9}, {%0,%1,%2,%3};"
        : "+f"(d[0]), "+f"(d[1]), "+f"(d[2]), "+f"(d[3])
        : "r"(a0), "r"(a1), "r"(a2), "r"(a3), "r"(b0), "r"(b1));
}

// ---------------------------------------------------------------------------
// Fused 2-layer MLP projection (unchanged from R1)
// ---------------------------------------------------------------------------
__global__ void __launch_bounds__(256) mlp_kernel(
    const float* __restrict__ x,
    const float* __restrict__ W1, const float* __restrict__ b1,
    const float* __restrict__ W2, const float* __restrict__ b2,
    int which, float scale)
{
    float* out = (which == 0) ? g_q : (which == 1) ? g_k : g_v;
    __shared__ float Xs[16][64];
    __shared__ float Hs[16][HID_];
    const int n0 = blockIdx.x * 16;
    const int t  = threadIdx.x;

    for (int i = t; i < 16 * 16; i += 256) {
        int r = i >> 4, c4 = (i & 15) * 4;
        float4 v = *(const float4*)(x + (size_t)(n0 + r) * 64 + c4);
        Xs[r][c4+0] = v.x; Xs[r][c4+1] = v.y; Xs[r][c4+2] = v.z; Xs[r][c4+3] = v.w;
    }
    __syncthreads();

    float acc[16];
    {
        float bv = b1[t];
        #pragma unroll
        for (int r = 0; r < 16; r++) acc[r] = bv;
    }
    #pragma unroll 4
    for (int k = 0; k < 64; k++) {
        float w = W1[k * HID_ + t];
        #pragma unroll
        for (int r = 0; r < 16; r++) acc[r] += Xs[r][k] * w;
    }
    #pragma unroll
    for (int r = 0; r < 16; r++) Hs[r][t] = fmaxf(acc[r], 0.0f);
    __syncthreads();

    float a0[16], a1[16];
    {
        float bv0 = b2[t], bv1 = b2[t + 256];
        #pragma unroll
        for (int r = 0; r < 16; r++) { a0[r] = bv0; a1[r] = bv1; }
    }
    #pragma unroll 2
    for (int k = 0; k < HID_; k++) {
        float w0 = W2[k * 512 + t];
        float w1 = W2[k * 512 + t + 256];
        #pragma unroll
        for (int r = 0; r < 16; r++) {
            float hh = Hs[r][k];
            a0[r] += hh * w0;
            a1[r] += hh * w1;
        }
    }
    const int j0 = t, j1 = t + 256;
    const int h0 = j0 >> 6, d0 = j0 & 63;
    const int h1 = j1 >> 6, d1 = j1 & 63;
    #pragma unroll
    for (int r = 0; r < 16; r++) {
        int n  = n0 + r;
        int tt = n >> 2;
        int bb = n & 3;
        out[((size_t)(bb * H_ + h0) * T_ + tt) * D_ + d0] = a0[r] * scale;
        out[((size_t)(bb * H_ + h1) * T_ + tt) * D_ + d1] = a1[r] * scale;
    }
}

// ---------------------------------------------------------------------------
// Flash attention with tf32 mma.sync tensor cores.
// BM=128 rows/block (8 warps x M=16 strips), BN=64 keys/iter.
// Register-resident online softmax (rows complete within 4-lane groups).
// ---------------------------------------------------------------------------
#define BM    128
#define BN    64
#define QPAD  68   // stride % 32 == 4 -> frag quad (4g+t) conflict-free
#define KPAD  68
#define VPAD  72   // stride % 32 == 8 -> frag quad (8t+g) conflict-free
#define PPAD  68

#define FLASH_SMEM ((BM*QPAD + BN*KPAD + BN*VPAD + BM*PPAD) * 4)

__global__ void __launch_bounds__(256, 2) flash_kernel(const float* __restrict__ mask)
{
    extern __shared__ float smf[];
    float* Qs = smf;                    // BM x QPAD (tf32)
    float* Ks = Qs + BM * QPAD;         // BN x KPAD (tf32)
    float* Vs = Ks + BN * KPAD;         // BN x VPAD (tf32)
    float* Ps = Vs + BN * VPAD;         // BM x PPAD: mask (fp32) then P (tf32)

    const int tb  = blockIdx.x, bh = blockIdx.y;
    const int b   = bh >> 3, h = bh & 7;
    const int t0  = tb * BM;
    const int tid = threadIdx.x;
    const int w   = tid >> 5, lane = tid & 31;
    const int g   = lane >> 2, t = lane & 3;
    const int m0  = w * 16;
    const int rA  = m0 + g, rB = rA + 8;

    const float* qp = g_q + (size_t)bh * T_ * D_ + (size_t)t0 * D_;
    const float* kp = g_k + (size_t)bh * S_ * D_;
    const float* vp = g_v + (size_t)bh * S_ * D_;
    const float* mp = mask + (size_t)b * T_ * S_ + (size_t)t0 * S_;

    // Q tile -> smem (tf32-rounded)
    for (int i = tid; i < BM * 16; i += 256) {
        int r = i >> 4, c = (i & 15) * 4;
        float4 v = *(const float4*)(qp + (size_t)r * D_ + c);
        float* q = Qs + r * QPAD + c;
        q[0] = to_tf32(v.x); q[1] = to_tf32(v.y);
        q[2] = to_tf32(v.z); q[3] = to_tf32(v.w);
    }

    float O[8][4];
    #pragma unroll
    for (int i = 0; i < 8; i++)
        #pragma unroll
        for (int j = 0; j < 4; j++) O[i][j] = 0.0f;
    float mstA = -3.0e38f, mstB = -3.0e38f, lA = 0.0f, lB = 0.0f;

    for (int s0 = 0; s0 < S_; s0 += BN) {
        __syncthreads();
        // K, V tiles (tf32-rounded)
        for (int i = tid; i < BN * 16; i += 256) {
            int r = i >> 4, c = (i & 15) * 4;
            float4 kv = *(const float4*)(kp + (size_t)(s0 + r) * D_ + c);
            float4 vv = *(const float4*)(vp + (size_t)(s0 + r) * D_ + c);
            float* kd = Ks + r * KPAD + c;
            kd[0] = to_tf32(kv.x); kd[1] = to_tf32(kv.y);
            kd[2] = to_tf32(kv.z); kd[3] = to_tf32(kv.w);
            float* vd = Vs + r * VPAD + c;
            vd[0] = to_tf32(vv.x); vd[1] = to_tf32(vv.y);
            vd[2] = to_tf32(vv.z); vd[3] = to_tf32(vv.w);
        }
        // mask tile -> Ps (fp32)
        for (int i = tid; i < BM * 16; i += 256) {
            int r = i >> 4, c = (i & 15) * 4;
            float4 mv = *(const float4*)(mp + (size_t)r * S_ + s0 + c);
            float* pd = Ps + r * PPAD + c;
            pd[0] = mv.x; pd[1] = mv.y; pd[2] = mv.z; pd[3] = mv.w;
        }
        __syncthreads();

        // ---- QK^T via tf32 mma: sc[nt] covers rows {rA,rB} x cols nt*8..+7
        float sc[8][4];
        #pragma unroll
        for (int i = 0; i < 8; i++)
            #pragma unroll
            for (int j = 0; j < 4; j++) sc[i][j] = 0.0f;

        #pragma unroll
        for (int kk = 0; kk < 8; kk++) {
            const int k0 = kk * 8;
            uint32_t a0 = fu(Qs[rA * QPAD + k0 + t]);
            uint32_t a1 = fu(Qs[rB * QPAD + k0 + t]);
            uint32_t a2 = fu(Qs[rA * QPAD + k0 + t + 4]);
            uint32_t a3 = fu(Qs[rB * QPAD + k0 + t + 4]);
            #pragma unroll
            for (int nt = 0; nt < 8; nt++) {
                uint32_t b0 = fu(Ks[(nt * 8 + g) * KPAD + k0 + t]);
                uint32_t b1 = fu(Ks[(nt * 8 + g) * KPAD + k0 + t + 4]);
                mma_tf32(sc[nt], a0, a1, a2, a3, b0, b1);
            }
        }

        // ---- add mask, register-resident online softmax
        float mxA = -3.0e38f, mxB = -3.0e38f;
        #pragma unroll
        for (int nt = 0; nt < 8; nt++) {
            float2 ma = *(const float2*)(Ps + rA * PPAD + nt * 8 + 2 * t);
            float2 mb = *(const float2*)(Ps + rB * PPAD + nt * 8 + 2 * t);
            sc[nt][0] += ma.x; sc[nt][1] += ma.y;
            sc[nt][2] += mb.x; sc[nt][3] += mb.y;
            mxA = fmaxf(mxA, fmaxf(sc[nt][0], sc[nt][1]));
            mxB = fmaxf(mxB, fmaxf(sc[nt][2], sc[nt][3]));
        }
        mxA = fmaxf(mxA, __shfl_xor_sync(0xffffffffu, mxA, 1));
        mxA = fmaxf(mxA, __shfl_xor_sync(0xffffffffu, mxA, 2));
        mxB = fmaxf(mxB, __shfl_xor_sync(0xffffffffu, mxB, 1));
        mxB = fmaxf(mxB, __shfl_xor_sync(0xffffffffu, mxB, 2));

        float nmA = fmaxf(mstA, mxA), nmB = fmaxf(mstB, mxB);
        float aA = __expf(mstA - nmA), aB = __expf(mstB - nmB);
        mstA = nmA; mstB = nmB;

        float sA = 0.0f, sB = 0.0f;
        #pragma unroll
        for (int nt = 0; nt < 8; nt++) {
            float p0 = __expf(sc[nt][0] - nmA);
            float p1 = __expf(sc[nt][1] - nmA);
            float p2 = __expf(sc[nt][2] - nmB);
            float p3 = __expf(sc[nt][3] - nmB);
            sA += p0 + p1; sB += p2 + p3;
            float2 w0 = make_float2(to_tf32(p0), to_tf32(p1));
            float2 w1 = make_float2(to_tf32(p2), to_tf32(p3));
            *(float2*)(Ps + rA * PPAD + nt * 8 + 2 * t) = w0;
            *(float2*)(Ps + rB * PPAD + nt * 8 + 2 * t) = w1;
        }
        sA += __shfl_xor_sync(0xffffffffu, sA, 1);
        sA += __shfl_xor_sync(0xffffffffu, sA, 2);
        sB += __shfl_xor_sync(0xffffffffu, sB, 1);
        sB += __shfl_xor_sync(0xffffffffu, sB, 2);
        lA = lA * aA + sA;
        lB = lB * aB + sB;

        #pragma unroll
        for (int nt = 0; nt < 8; nt++) {
            O[nt][0] *= aA; O[nt][1] *= aA;
            O[nt][2] *= aB; O[nt][3] *= aB;
        }
        __syncwarp();   // P strip written & read within this warp only

        // ---- P V via tf32 mma
        #pragma unroll
        for (int kk = 0; kk < 8; kk++) {
            const int k0 = kk * 8;
            uint32_t a0 = fu(Ps[rA * PPAD + k0 + t]);
            uint32_t a1 = fu(Ps[rB * PPAD + k0 + t]);
            uint32_t a2 = fu(Ps[rA * PPAD + k0 + t + 4]);
            uint32_t a3 = fu(Ps[rB * PPAD + k0 + t + 4]);
            #pragma unroll
            for (int nt = 0; nt < 8; nt++) {
                uint32_t b0 = fu(Vs[(k0 + t) * VPAD + nt * 8 + g]);
                uint32_t b1 = fu(Vs[(k0 + t + 4) * VPAD + nt * 8 + g]);
                mma_tf32(O[nt], a0, a1, a2, a3, b0, b1);
            }
        }
    }

    // epilogue: normalize, scatter to ctx[(t*B+b)][h*64+c]
    float iA = 1.0f / lA, iB = 1.0f / lB;
    size_t rowA = (size_t)(t0 + rA) * B_ + b;
    size_t rowB = (size_t)(t0 + rB) * B_ + b;
    #pragma unroll
    for (int nt = 0; nt < 8; nt++) {
        *(float2*)(g_ctx + rowA * (H_ * D_) + h * D_ + nt * 8 + 2 * t) =
            make_float2(O[nt][0] * iA, O[nt][1] * iA);
        *(float2*)(g_ctx + rowB * (H_ * D_) + h * D_ + nt * 8 + 2 * t) =
            make_float2(O[nt][2] * iB, O[nt][3] * iB);
    }
}

// ---------------------------------------------------------------------------
// Output projection (unchanged)
// ---------------------------------------------------------------------------
__global__ void __launch_bounds__(256) outproj_kernel(
    const float* __restrict__ Wo, const float* __restrict__ bo,
    float* __restrict__ out)
{
    const int n0 = blockIdx.x * 32;
    const int j  = threadIdx.x & 63;
    const int rg = threadIdx.x >> 6;
    float acc[8];
    {
        float bv = bo[j];
        #pragma unroll
        for (int i = 0; i < 8; i++) acc[i] = bv;
    }
    for (int k = 0; k < 512; k += 4) {
        float w0 = Wo[(k + 0) * 64 + j];
        float w1 = Wo[(k + 1) * 64 + j];
        float w2 = Wo[(k + 2) * 64 + j];
        float w3 = Wo[(k + 3) * 64 + j];
        #pragma unroll
        for (int i = 0; i < 8; i++) {
            const float4 cv = *(const float4*)(g_ctx + (size_t)(n0 + rg * 8 + i) * 512 + k);
            acc[i] += cv.x * w0 + cv.y * w1 + cv.z * w2 + cv.w * w3;
        }
    }
    #pragma unroll
    for (int i = 0; i < 8; i++)
        out[(size_t)(n0 + rg * 8 + i) * 64 + j] = acc[i];
}

// ---------------------------------------------------------------------------
extern "C" void kernel_launch(void* const* d_in, const int* in_sizes, int n_in,
                              void* d_out, int out_size)
{
    const float* query = (const float*)d_in[0];
    const float* key   = (const float*)d_in[1];
    const float* value = (const float*)d_in[2];
    const float* mask  = (const float*)d_in[3];
    const float* Wq1 = (const float*)d_in[4];
    const float* bq1 = (const float*)d_in[5];
    const float* Wq2 = (const float*)d_in[6];
    const float* bq2 = (const float*)d_in[7];
    const float* Wk1 = (const float*)d_in[8];
    const float* bk1 = (const float*)d_in[9];
    const float* Wk2 = (const float*)d_in[10];
    const float* bk2 = (const float*)d_in[11];
    const float* Wv1 = (const float*)d_in[12];
    const float* bv1 = (const float*)d_in[13];
    const float* Wv2 = (const float*)d_in[14];
    const float* bv2 = (const float*)d_in[15];
    const float* Wo  = (const float*)d_in[16];
    const float* bo  = (const float*)d_in[17];
    float* out = (float*)d_out;

    const float scaling = 0.125f;   // DQ^-0.5

    dim3 mlpGrid(NROW_ / 16);
    mlp_kernel<<<mlpGrid, 256>>>(query, Wq1, bq1, Wq2, bq2, 0, scaling);
    mlp_kernel<<<mlpGrid, 256>>>(key,   Wk1, bk1, Wk2, bk2, 1, 1.0f);
    mlp_kernel<<<mlpGrid, 256>>>(value, Wv1, bv1, Wv2, bv2, 2, 1.0f);

    cudaFuncSetAttribute(flash_kernel,
                         cudaFuncAttributeMaxDynamicSharedMemorySize, FLASH_SMEM);
    dim3 fGrid(T_ / BM, B_ * H_);
    flash_kernel<<<fGrid, 256, FLASH_SMEM>>>(mask);

    outproj_kernel<<<NROW_ / 32, 256>>>(Wo, bo, out);
}

// round 3
// speedup vs baseline: 2.8661x; 1.5877x over previous
#include <cuda_runtime.h>
#include <cuda_bf16.h>
#include <math.h>
#include <stdint.h>

#define H_    8
#define D_    64
#define HID_  256
#define T_    2048
#define S_    2048
#define B_    4
#define NROW_ (T_*B_)
#define LOG2E 1.44269504f

// Scratch (allocation-free): projections in bf16, ctx fp32
__device__ __nv_bfloat16 g_q[B_*H_*T_*D_];
__device__ __nv_bfloat16 g_k[B_*H_*S_*D_];
__device__ __nv_bfloat16 g_v[B_*H_*S_*D_];
__device__ float g_ctx[NROW_*H_*D_];

__device__ __forceinline__ uint32_t smem_u32(const void* p) {
    return (uint32_t)__cvta_generic_to_shared(p);
}
__device__ __forceinline__ void ldsm_x4(uint32_t& r0, uint32_t& r1,
                                        uint32_t& r2, uint32_t& r3, uint32_t a) {
    asm volatile("ldmatrix.sync.aligned.m8n8.x4.shared.b16 {%0,%1,%2,%3}, [%4];"
                 : "=r"(r0), "=r"(r1), "=r"(r2), "=r"(r3) : "r"(a));
}
__device__ __forceinline__ void ldsm_x2(uint32_t& r0, uint32_t& r1, uint32_t a) {
    asm volatile("ldmatrix.sync.aligned.m8n8.x2.shared.b16 {%0,%1}, [%2];"
                 : "=r"(r0), "=r"(r1) : "r"(a));
}
__device__ __forceinline__ void ldsm_x2t(uint32_t& r0, uint32_t& r1, uint32_t a) {
    asm volatile("ldmatrix.sync.aligned.m8n8.x2.trans.shared.b16 {%0,%1}, [%2];"
                 : "=r"(r0), "=r"(r1) : "r"(a));
}
__device__ __forceinline__ void mma_bf16(float* d,
    uint32_t a0, uint32_t a1, uint32_t a2, uint32_t a3, uint32_t b0, uint32_t b1)
{
    asm volatile(
        "mma.sync.aligned.m16n8k16.row.col.f32.bf16.bf16.f32 "
        "{%0,%1,%2,%3}, {%4,%5,%6,%7}, {%8,%9}, {%0,%1,%2,%3};"
        : "+f"(d[0]), "+f"(d[1]), "+f"(d[2]), "+f"(d[3])
        : "r"(a0), "r"(a1), "r"(a2), "r"(a3), "r"(b0), "r"(b1));
}
__device__ __forceinline__ uint32_t bf16x2(float lo, float hi) {
    uint32_t r;
    asm("cvt.rn.bf16x2.f32 %0, %1, %2;" : "=r"(r) : "f"(hi), "f"(lo));
    return r;
}

// ---------------------------------------------------------------------------
// Fused 2-layer MLP projection; vectorized LDS (1:4 LDS:FFMA); bf16 output.
// ---------------------------------------------------------------------------
__global__ void __launch_bounds__(256) mlp_kernel(
    const float* __restrict__ x,
    const float* __restrict__ W1, const float* __restrict__ b1,
    const float* __restrict__ W2, const float* __restrict__ b2,
    int which, float scale)
{
    __nv_bfloat16* out = (which == 0) ? g_q : (which == 1) ? g_k : g_v;
    __shared__ float Xs[16][64];
    __shared__ float Hs[16][HID_];
    const int n0 = blockIdx.x * 16;
    const int t  = threadIdx.x;

    for (int i = t; i < 16 * 16; i += 256) {
        int r = i >> 4, c4 = (i & 15) * 4;
        *(float4*)&Xs[r][c4] = *(const float4*)(x + (size_t)(n0 + r) * 64 + c4);
    }
    __syncthreads();

    float acc[16];
    {
        float bv = b1[t];
        #pragma unroll
        for (int r = 0; r < 16; r++) acc[r] = bv;
    }
    #pragma unroll 4
    for (int k4 = 0; k4 < 64; k4 += 4) {
        float w0 = W1[(k4+0) * HID_ + t];
        float w1 = W1[(k4+1) * HID_ + t];
        float w2 = W1[(k4+2) * HID_ + t];
        float w3 = W1[(k4+3) * HID_ + t];
        #pragma unroll
        for (int r = 0; r < 16; r++) {
            float4 xv = *(const float4*)&Xs[r][k4];
            acc[r] += xv.x * w0 + xv.y * w1 + xv.z * w2 + xv.w * w3;
        }
    }
    #pragma unroll
    for (int r = 0; r < 16; r++) Hs[r][t] = fmaxf(acc[r], 0.0f);
    __syncthreads();

    float a0[16], a1[16];
    {
        float bv0 = b2[t], bv1 = b2[t + 256];
        #pragma unroll
        for (int r = 0; r < 16; r++) { a0[r] = bv0; a1[r] = bv1; }
    }
    #pragma unroll 2
    for (int k4 = 0; k4 < HID_; k4 += 4) {
        float w00 = W2[(k4+0)*512 + t],       w10 = W2[(k4+0)*512 + t + 256];
        float w01 = W2[(k4+1)*512 + t],       w11 = W2[(k4+1)*512 + t + 256];
        float w02 = W2[(k4+2)*512 + t],       w12 = W2[(k4+2)*512 + t + 256];
        float w03 = W2[(k4+3)*512 + t],       w13 = W2[(k4+3)*512 + t + 256];
        #pragma unroll
        for (int r = 0; r < 16; r++) {
            float4 hv = *(const float4*)&Hs[r][k4];
            a0[r] += hv.x * w00 + hv.y * w01 + hv.z * w02 + hv.w * w03;
            a1[r] += hv.x * w10 + hv.y * w11 + hv.z * w12 + hv.w * w13;
        }
    }
    const int j0 = t, j1 = t + 256;
    const int h0 = j0 >> 6, d0 = j0 & 63;
    const int h1 = j1 >> 6, d1 = j1 & 63;
    #pragma unroll
    for (int r = 0; r < 16; r++) {
        int n  = n0 + r;
        int tt = n >> 2;
        int bb = n & 3;
        out[((size_t)(bb * H_ + h0) * T_ + tt) * D_ + d0] =
            __float2bfloat16_rn(a0[r] * scale);
        out[((size_t)(bb * H_ + h1) * T_ + tt) * D_ + d1] =
            __float2bfloat16_rn(a1[r] * scale);
    }
}

// ---------------------------------------------------------------------------
// Flash attention, bf16 mma m16n8k16 + ldmatrix, exp2-based online softmax.
// BM=128 (8 warps x M16), BN=64. Q fragments hoisted to registers.
// Smem rows: bf16 stride 72 (144B = 36 banks, ≡4 mod 32 -> LDSM conflict-free);
// mask fp32 stride 68. Mask buffer aliases the Q staging buffer.
// ---------------------------------------------------------------------------
#define BM    128
#define BN    64
#define BSTR  72
#define MSTR  68

#define OFF_MS   0
#define OFF_KS   (BM*MSTR*4)                 // 34816
#define OFF_VS   (OFF_KS + BN*BSTR*2)        // +9216
#define OFF_PS   (OFF_VS + BN*BSTR*2)        // +9216
#define FLASH_SMEM (OFF_PS + BM*BSTR*2)      // 71680

__global__ void __launch_bounds__(256, 2) flash_kernel(const float* __restrict__ mask)
{
    extern __shared__ char sm[];
    float*         Ms  = (float*)(sm + OFF_MS);
    __nv_bfloat16* Qst = (__nv_bfloat16*)(sm + OFF_MS);   // alias (pre-loop only)
    __nv_bfloat16* Ks  = (__nv_bfloat16*)(sm + OFF_KS);
    __nv_bfloat16* Vs  = (__nv_bfloat16*)(sm + OFF_VS);
    __nv_bfloat16* Ps  = (__nv_bfloat16*)(sm + OFF_PS);

    const int tb  = blockIdx.x, bh = blockIdx.y;
    const int b   = bh >> 3, h = bh & 7;
    const int t0  = tb * BM;
    const int tid = threadIdx.x;
    const int w   = tid >> 5, lane = tid & 31;
    const int g   = lane >> 2, t = lane & 3;
    const int m0  = w * 16;
    const int rA  = m0 + g, rB = rA + 8;

    const __nv_bfloat16* qp = g_q + (size_t)bh * T_ * D_ + (size_t)t0 * D_;
    const __nv_bfloat16* kp = g_k + (size_t)bh * S_ * D_;
    const __nv_bfloat16* vp = g_v + (size_t)bh * S_ * D_;
    const float* mp = mask + (size_t)b * T_ * S_ + (size_t)t0 * S_;

    // ---- stage Q (bf16) and hoist A-fragments into registers
    for (int i = tid; i < BM * 8; i += 256) {
        int r = i >> 3, c8 = (i & 7) * 8;
        *(uint4*)(Qst + r * BSTR + c8) = *(const uint4*)(qp + (size_t)r * D_ + c8);
    }
    __syncthreads();
    uint32_t qf[4][4];
    {
        int row = m0 + (lane & 15);
        int chalf = (lane >> 4) * 8;
        #pragma unroll
        for (int kk = 0; kk < 4; kk++) {
            uint32_t a = smem_u32(Qst + row * BSTR + kk * 16 + chalf);
            ldsm_x4(qf[kk][0], qf[kk][1], qf[kk][2], qf[kk][3], a);
        }
    }
    __syncthreads();

    float O[8][4];
    #pragma unroll
    for (int i = 0; i < 8; i++)
        #pragma unroll
        for (int j = 0; j < 4; j++) O[i][j] = 0.0f;
    float mstA = -3.0e38f, mstB = -3.0e38f, lA = 0.0f, lB = 0.0f;

    // precomputed LDSM lane addresses (element offsets)
    const int kv_row = lane & 7;                  // + nt*8
    const int kv_ch  = ((lane >> 3) & 1) * 8;     // k-half
    const int p_row  = m0 + (lane & 15);
    const int p_ch   = (lane >> 4) * 8;
    const int v_row  = lane & 15;                 // + kk*16

    for (int s0 = 0; s0 < S_; s0 += BN) {
        __syncthreads();
        // stage K, V (bf16 uint4 copies)
        for (int i = tid; i < BN * 8; i += 256) {
            int r = i >> 3, c8 = (i & 7) * 8;
            *(uint4*)(Ks + r * BSTR + c8) =
                *(const uint4*)(kp + (size_t)(s0 + r) * D_ + c8);
            *(uint4*)(Vs + r * BSTR + c8) =
                *(const uint4*)(vp + (size_t)(s0 + r) * D_ + c8);
        }
        // stage mask * log2e (fp32)
        for (int i = tid; i < BM * 16; i += 256) {
            int r = i >> 4, c4 = (i & 15) * 4;
            float4 mv = *(const float4*)(mp + (size_t)r * S_ + s0 + c4);
            mv.x *= LOG2E; mv.y *= LOG2E; mv.z *= LOG2E; mv.w *= LOG2E;
            *(float4*)&Ms[r * MSTR + c4] = mv;
        }
        __syncthreads();

        // ---- QK^T
        float sc[8][4];
        #pragma unroll
        for (int i = 0; i < 8; i++)
            #pragma unroll
            for (int j = 0; j < 4; j++) sc[i][j] = 0.0f;

        #pragma unroll
        for (int kk = 0; kk < 4; kk++) {
            uint32_t kb0[8], kb1[8];
            #pragma unroll
            for (int nt = 0; nt < 8; nt++) {
                uint32_t a = smem_u32(Ks + (nt * 8 + kv_row) * BSTR + kk * 16 + kv_ch);
                ldsm_x2(kb0[nt], kb1[nt], a);
            }
            #pragma unroll
            for (int nt = 0; nt < 8; nt++)
                mma_bf16(sc[nt], qf[kk][0], qf[kk][1], qf[kk][2], qf[kk][3],
                         kb0[nt], kb1[nt]);
        }

        // ---- mask add + register-resident online softmax (base 2)
        float mxA = -3.0e38f, mxB = -3.0e38f;
        #pragma unroll
        for (int nt = 0; nt < 8; nt++) {
            float2 ma = *(const float2*)(Ms + rA * MSTR + nt * 8 + 2 * t);
            float2 mb = *(const float2*)(Ms + rB * MSTR + nt * 8 + 2 * t);
            sc[nt][0] += ma.x; sc[nt][1] += ma.y;
            sc[nt][2] += mb.x; sc[nt][3] += mb.y;
            mxA = fmaxf(mxA, fmaxf(sc[nt][0], sc[nt][1]));
            mxB = fmaxf(mxB, fmaxf(sc[nt][2], sc[nt][3]));
        }
        mxA = fmaxf(mxA, __shfl_xor_sync(0xffffffffu, mxA, 1));
        mxA = fmaxf(mxA, __shfl_xor_sync(0xffffffffu, mxA, 2));
        mxB = fmaxf(mxB, __shfl_xor_sync(0xffffffffu, mxB, 1));
        mxB = fmaxf(mxB, __shfl_xor_sync(0xffffffffu, mxB, 2));

        float nmA = fmaxf(mstA, mxA), nmB = fmaxf(mstB, mxB);
        float aA = exp2f(mstA - nmA), aB = exp2f(mstB - nmB);
        mstA = nmA; mstB = nmB;

        float sA = 0.0f, sB = 0.0f;
        #pragma unroll
        for (int nt = 0; nt < 8; nt++) {
            float p0 = exp2f(sc[nt][0] - nmA);
            float p1 = exp2f(sc[nt][1] - nmA);
            float p2 = exp2f(sc[nt][2] - nmB);
            float p3 = exp2f(sc[nt][3] - nmB);
            sA += p0 + p1; sB += p2 + p3;
            *(uint32_t*)(Ps + rA * BSTR + nt * 8 + 2 * t) = bf16x2(p0, p1);
            *(uint32_t*)(Ps + rB * BSTR + nt * 8 + 2 * t) = bf16x2(p2, p3);
        }
        sA += __shfl_xor_sync(0xffffffffu, sA, 1);
        sA += __shfl_xor_sync(0xffffffffu, sA, 2);
        sB += __shfl_xor_sync(0xffffffffu, sB, 1);
        sB += __shfl_xor_sync(0xffffffffu, sB, 2);
        lA = lA * aA + sA;
        lB = lB * aB + sB;

        #pragma unroll
        for (int nt = 0; nt < 8; nt++) {
            O[nt][0] *= aA; O[nt][1] *= aA;
            O[nt][2] *= aB; O[nt][3] *= aB;
        }
        __syncwarp();   // P strip produced & consumed within this warp

        // ---- P V
        #pragma unroll
        for (int kk = 0; kk < 4; kk++) {
            uint32_t pa0, pa1, pa2, pa3;
            ldsm_x4(pa0, pa1, pa2, pa3,
                    smem_u32(Ps + p_row * BSTR + kk * 16 + p_ch));
            uint32_t vb0[8], vb1[8];
            #pragma unroll
            for (int nt = 0; nt < 8; nt++) {
                uint32_t a = smem_u32(Vs + (kk * 16 + v_row) * BSTR + nt * 8);
                ldsm_x2t(vb0[nt], vb1[nt], a);
            }
            #pragma unroll
            for (int nt = 0; nt < 8; nt++)
                mma_bf16(O[nt], pa0, pa1, pa2, pa3, vb0[nt], vb1[nt]);
        }
    }

    // epilogue: normalize, scatter to ctx[(t*B+b)][h*64+c]
    float iA = 1.0f / lA, iB = 1.0f / lB;
    size_t rowA = (size_t)(t0 + rA) * B_ + b;
    size_t rowB = (size_t)(t0 + rB) * B_ + b;
    #pragma unroll
    for (int nt = 0; nt < 8; nt++) {
        *(float2*)(g_ctx + rowA * (H_ * D_) + h * D_ + nt * 8 + 2 * t) =
            make_float2(O[nt][0] * iA, O[nt][1] * iA);
        *(float2*)(g_ctx + rowB * (H_ * D_) + h * D_ + nt * 8 + 2 * t) =
            make_float2(O[nt][2] * iB, O[nt][3] * iB);
    }
}

// ---------------------------------------------------------------------------
// Output projection: out[8192,64] = ctx[8192,512] @ Wo[512,64] + bo (fp32)
// ---------------------------------------------------------------------------
__global__ void __launch_bounds__(256) outproj_kernel(
    const float* __restrict__ Wo, const float* __restrict__ bo,
    float* __restrict__ out)
{
    const int n0 = blockIdx.x * 32;
    const int j  = threadIdx.x & 63;
    const int rg = threadIdx.x >> 6;
    float acc[8];
    {
        float bv = bo[j];
        #pragma unroll
        for (int i = 0; i < 8; i++) acc[i] = bv;
    }
    for (int k = 0; k < 512; k += 4) {
        float w0 = Wo[(k + 0) * 64 + j];
        float w1 = Wo[(k + 1) * 64 + j];
        float w2 = Wo[(k + 2) * 64 + j];
        float w3 = Wo[(k + 3) * 64 + j];
        #pragma unroll
        for (int i = 0; i < 8; i++) {
            const float4 cv = *(const float4*)(g_ctx + (size_t)(n0 + rg * 8 + i) * 512 + k);
            acc[i] += cv.x * w0 + cv.y * w1 + cv.z * w2 + cv.w * w3;
        }
    }
    #pragma unroll
    for (int i = 0; i < 8; i++)
        out[(size_t)(n0 + rg * 8 + i) * 64 + j] = acc[i];
}

// ---------------------------------------------------------------------------
extern "C" void kernel_launch(void* const* d_in, const int* in_sizes, int n_in,
                              void* d_out, int out_size)
{
    const float* query = (const float*)d_in[0];
    const float* key   = (const float*)d_in[1];
    const float* value = (const float*)d_in[2];
    const float* mask  = (const float*)d_in[3];
    const float* Wq1 = (const float*)d_in[4];
    const float* bq1 = (const float*)d_in[5];
    const float* Wq2 = (const float*)d_in[6];
    const float* bq2 = (const float*)d_in[7];
    const float* Wk1 = (const float*)d_in[8];
    const float* bk1 = (const float*)d_in[9];
    const float* Wk2 = (const float*)d_in[10];
    const float* bk2 = (const float*)d_in[11];
    const float* Wv1 = (const float*)d_in[12];
    const float* bv1 = (const float*)d_in[13];
    const float* Wv2 = (const float*)d_in[14];
    const float* bv2 = (const float*)d_in[15];
    const float* Wo  = (const float*)d_in[16];
    const float* bo  = (const float*)d_in[17];
    float* out = (float*)d_out;

    const float qscale = 0.125f * LOG2E;   // DQ^-0.5 folded with log2(e)

    dim3 mlpGrid(NROW_ / 16);
    mlp_kernel<<<mlpGrid, 256>>>(query, Wq1, bq1, Wq2, bq2, 0, qscale);
    mlp_kernel<<<mlpGrid, 256>>>(key,   Wk1, bk1, Wk2, bk2, 1, 1.0f);
    mlp_kernel<<<mlpGrid, 256>>>(value, Wv1, bv1, Wv2, bv2, 2, 1.0f);

    cudaFuncSetAttribute(flash_kernel,
                         cudaFuncAttributeMaxDynamicSharedMemorySize, FLASH_SMEM);
    dim3 fGrid(T_ / BM, B_ * H_);
    flash_kernel<<<fGrid, 256, FLASH_SMEM>>>(mask);

    outproj_kernel<<<NROW_ / 32, 256>>>(Wo, bo, out);
}

// round 5
// speedup vs baseline: 3.9353x; 1.3730x over previous
#include <cuda_runtime.h>
#include <cuda_bf16.h>
#include <math.h>
#include <stdint.h>

#define H_    8
#define D_    64
#define HID_  256
#define T_    2048
#define S_    2048
#define B_    4
#define NROW_ (T_*B_)
#define LOG2E 1.44269504f

// Scratch (allocation-free)
__device__ __nv_bfloat16 g_q[B_*H_*T_*D_];
__device__ __nv_bfloat16 g_k[B_*H_*S_*D_];
__device__ __nv_bfloat16 g_v[B_*H_*S_*D_];
__device__ float g_ctx[NROW_*H_*D_];
// mask, bf16x2-packed in fragment-direct layout:
// [b*512 + tb*32 + sb][nt(8)][row(128)][t(4)] as uint32 (lo=col 2t, hi=col 2t+1)
__device__ uint32_t g_m2[(size_t)B_*16*32*4096];

__device__ __forceinline__ uint32_t smem_u32(const void* p) {
    return (uint32_t)__cvta_generic_to_shared(p);
}
__device__ __forceinline__ float to_tf32(float x) {
    float r; asm("cvt.rna.tf32.f32 %0, %1;" : "=f"(r) : "f"(x)); return r;
}
__device__ __forceinline__ uint32_t fu(float x) { return __float_as_uint(x); }
__device__ __forceinline__ float ex2(float x) {
    float r; asm("ex2.approx.ftz.f32 %0, %1;" : "=f"(r) : "f"(x)); return r;
}
__device__ __forceinline__ void ldsm_x4(uint32_t& r0, uint32_t& r1,
                                        uint32_t& r2, uint32_t& r3, uint32_t a) {
    asm volatile("ldmatrix.sync.aligned.m8n8.x4.shared.b16 {%0,%1,%2,%3}, [%4];"
                 : "=r"(r0), "=r"(r1), "=r"(r2), "=r"(r3) : "r"(a));
}
__device__ __forceinline__ void ldsm_x4t(uint32_t& r0, uint32_t& r1,
                                         uint32_t& r2, uint32_t& r3, uint32_t a) {
    asm volatile("ldmatrix.sync.aligned.m8n8.x4.trans.shared.b16 {%0,%1,%2,%3}, [%4];"
                 : "=r"(r0), "=r"(r1), "=r"(r2), "=r"(r3) : "r"(a));
}
__device__ __forceinline__ void mma_bf16(float* d,
    uint32_t a0, uint32_t a1, uint32_t a2, uint32_t a3, uint32_t b0, uint32_t b1)
{
    asm volatile(
        "mma.sync.aligned.m16n8k16.row.col.f32.bf16.bf16.f32 "
        "{%0,%1,%2,%3}, {%4,%5,%6,%7}, {%8,%9}, {%0,%1,%2,%3};"
        : "+f"(d[0]), "+f"(d[1]), "+f"(d[2]), "+f"(d[3])
        : "r"(a0), "r"(a1), "r"(a2), "r"(a3), "r"(b0), "r"(b1));
}
__device__ __forceinline__ void mma_tf32(float* d,
    uint32_t a0, uint32_t a1, uint32_t a2, uint32_t a3, uint32_t b0, uint32_t b1)
{
    asm volatile(
        "mma.sync.aligned.m16n8k8.row.col.f32.tf32.tf32.f32 "
        "{%0,%1,%2,%3}, {%4,%5,%6,%7}, {%8,%9}, {%0,%1,%2,%3};"
        : "+f"(d[0]), "+f"(d[1]), "+f"(d[2]), "+f"(d[3])
        : "r"(a0), "r"(a1), "r"(a2), "r"(a3), "r"(b0), "r"(b1));
}
__device__ __forceinline__ uint32_t bf16x2(float lo, float hi) {
    uint32_t r;
    asm("cvt.rn.bf16x2.f32 %0, %1, %2;" : "=r"(r) : "f"(hi), "f"(lo));
    return r;
}
__device__ __forceinline__ void cp16(uint32_t dst, const void* src) {
    asm volatile("cp.async.cg.shared.global [%0], [%1], 16;"
                 :: "r"(dst), "l"(src));
}
#define CP_COMMIT asm volatile("cp.async.commit_group;")
#define CP_WAIT0  asm volatile("cp.async.wait_group 0;")

// ---------------------------------------------------------------------------
// Mask pre-pack: mask[b][t][s] fp32 -> bf16x2 * log2e in fragment layout.
// grid: B_*16*32 tiles (128x64 each), 256 threads.
// ---------------------------------------------------------------------------
__global__ void __launch_bounds__(256) mask_prep_kernel(const float* __restrict__ mask)
{
    const int tile = blockIdx.x;
    const int b  = tile >> 9;
    const int tb = (tile >> 5) & 15;
    const int sb = tile & 31;
    const float* mp = mask + (size_t)b * T_ * S_ + (size_t)(tb * 128) * S_ + sb * 64;
    uint32_t* op = g_m2 + (size_t)tile * 4096;
    const int tid = threadIdx.x;
    #pragma unroll
    for (int it = 0; it < 16; it++) {
        int idx = tid + it * 256;
        int r = idx >> 5, cp = idx & 31;
        float2 mv = *(const float2*)(mp + (size_t)r * S_ + cp * 2);
        op[(cp >> 2) * 512 + r * 4 + (cp & 3)] =
            bf16x2(mv.x * LOG2E, mv.y * LOG2E);
    }
}

// ---------------------------------------------------------------------------
// MLP via tf32 mma: block = 32 rows, 8 warps; layer1 n-split 8x32,
// layer2 n-split 8x64 (head h == warp id). grid (256, 3).
// ---------------------------------------------------------------------------
__global__ void __launch_bounds__(256) mlp_mma_kernel(
    const float* __restrict__ xq, const float* __restrict__ xk,
    const float* __restrict__ xv,
    const float* __restrict__ Wq1, const float* __restrict__ bq1,
    const float* __restrict__ Wq2, const float* __restrict__ bq2,
    const float* __restrict__ Wk1, const float* __restrict__ bk1,
    const float* __restrict__ Wk2, const float* __restrict__ bk2,
    const float* __restrict__ Wv1, const float* __restrict__ bv1,
    const float* __restrict__ Wv2, const float* __restrict__ bv2)
{
    const int which = blockIdx.y;
    const float *x, *W1, *b1v, *W2, *b2v;
    __nv_bfloat16* outp;
    float scale;
    if (which == 0) { x=xq; W1=Wq1; b1v=bq1; W2=Wq2; b2v=bq2; outp=g_q; scale=0.125f*LOG2E; }
    else if (which == 1) { x=xk; W1=Wk1; b1v=bk1; W2=Wk2; b2v=bk2; outp=g_k; scale=1.0f; }
    else { x=xv; W1=Wv1; b1v=bv1; W2=Wv2; b2v=bv2; outp=g_v; scale=1.0f; }

    __shared__ float Xs[32][68];
    __shared__ float Hs[32][260];

    const int n0r = blockIdx.x * 32;
    const int tid = threadIdx.x;
    const int w = tid >> 5, lane = tid & 31;
    const int g = lane >> 2, t = lane & 3;

    // load X tile [32][64] (tf32-rounded)
    for (int i = tid; i < 32 * 16; i += 256) {
        int r = i >> 4, c4 = (i & 15) * 4;
        float4 v = *(const float4*)(x + (size_t)(n0r + r) * 64 + c4);
        v.x = to_tf32(v.x); v.y = to_tf32(v.y);
        v.z = to_tf32(v.z); v.w = to_tf32(v.w);
        *(float4*)&Xs[r][c4] = v;
    }
    __syncthreads();

    // ---- layer 1: H = relu(X @ W1 + b1); warp covers cols [w*32, w*32+32)
    {
        float acc[2][4][4];
        #pragma unroll
        for (int mt = 0; mt < 2; mt++)
            #pragma unroll
            for (int nt = 0; nt < 4; nt++)
                #pragma unroll
                for (int j = 0; j < 4; j++) acc[mt][nt][j] = 0.0f;

        const int n0 = w * 32;
        #pragma unroll
        for (int k0 = 0; k0 < 64; k0 += 8) {
            uint32_t a[2][4];
            #pragma unroll
            for (int mt = 0; mt < 2; mt++) {
                int rA_ = mt * 16 + g;
                a[mt][0] = fu(Xs[rA_][k0 + t]);
                a[mt][1] = fu(Xs[rA_ + 8][k0 + t]);
                a[mt][2] = fu(Xs[rA_][k0 + t + 4]);
                a[mt][3] = fu(Xs[rA_ + 8][k0 + t + 4]);
            }
            #pragma unroll
            for (int nt = 0; nt < 4; nt++) {
                int n = n0 + nt * 8 + g;
                uint32_t b0 = fu(to_tf32(W1[(k0 + t) * HID_ + n]));
                uint32_t b1f = fu(to_tf32(W1[(k0 + t + 4) * HID_ + n]));
                mma_tf32(acc[0][nt], a[0][0], a[0][1], a[0][2], a[0][3], b0, b1f);
                mma_tf32(acc[1][nt], a[1][0], a[1][1], a[1][2], a[1][3], b0, b1f);
            }
        }
        // bias + relu -> Hs (tf32-rounded)
        #pragma unroll
        for (int nt = 0; nt < 4; nt++) {
            int j = n0 + nt * 8 + 2 * t;
            float bz0 = b1v[j], bz1 = b1v[j + 1];
            #pragma unroll
            for (int mt = 0; mt < 2; mt++) {
                int rA_ = mt * 16 + g;
                float2 v0 = make_float2(
                    to_tf32(fmaxf(acc[mt][nt][0] + bz0, 0.0f)),
                    to_tf32(fmaxf(acc[mt][nt][1] + bz1, 0.0f)));
                float2 v1 = make_float2(
                    to_tf32(fmaxf(acc[mt][nt][2] + bz0, 0.0f)),
                    to_tf32(fmaxf(acc[mt][nt][3] + bz1, 0.0f)));
                *(float2*)&Hs[rA_][j] = v0;
                *(float2*)&Hs[rA_ + 8][j] = v1;
            }
        }
    }
    __syncthreads();

    // ---- layer 2: Y = H @ W2 + b2; warp covers cols [w*64, w*64+64) -> head w
    {
        float acc[2][8][4];
        #pragma unroll
        for (int mt = 0; mt < 2; mt++)
            #pragma unroll
            for (int nt = 0; nt < 8; nt++)
                #pragma unroll
                for (int j = 0; j < 4; j++) acc[mt][nt][j] = 0.0f;

        const int n0 = w * 64;
        #pragma unroll 4
        for (int k0 = 0; k0 < HID_; k0 += 8) {
            uint32_t a[2][4];
            #pragma unroll
            for (int mt = 0; mt < 2; mt++) {
                int rA_ = mt * 16 + g;
                a[mt][0] = fu(Hs[rA_][k0 + t]);
                a[mt][1] = fu(Hs[rA_ + 8][k0 + t]);
                a[mt][2] = fu(Hs[rA_][k0 + t + 4]);
                a[mt][3] = fu(Hs[rA_ + 8][k0 + t + 4]);
            }
            #pragma unroll
            for (int nt = 0; nt < 8; nt++) {
                int n = n0 + nt * 8 + g;
                uint32_t b0 = fu(to_tf32(W2[(k0 + t) * 512 + n]));
                uint32_t b1f = fu(to_tf32(W2[(k0 + t + 4) * 512 + n]));
                mma_tf32(acc[0][nt], a[0][0], a[0][1], a[0][2], a[0][3], b0, b1f);
                mma_tf32(acc[1][nt], a[1][0], a[1][1], a[1][2], a[1][3], b0, b1f);
            }
        }
        // epilogue: bias, scale, bf16x2 scatter to [(b*H+w)*T + tt][d]
        #pragma unroll
        for (int nt = 0; nt < 8; nt++) {
            int d = nt * 8 + 2 * t;
            float bz0 = b2v[n0 + d], bz1 = b2v[n0 + d + 1];
            #pragma unroll
            for (int mt = 0; mt < 2; mt++) {
                #pragma unroll
                for (int half = 0; half < 2; half++) {
                    int nrow = n0r + mt * 16 + g + half * 8;
                    int tt = nrow >> 2, bb = nrow & 3;
                    float v0 = (acc[mt][nt][half * 2 + 0] + bz0) * scale;
                    float v1 = (acc[mt][nt][half * 2 + 1] + bz1) * scale;
                    *(uint32_t*)(outp + ((size_t)(bb * H_ + w) * T_ + tt) * D_ + d) =
                        bf16x2(v0, v1);
                }
            }
        }
    }
}

// ---------------------------------------------------------------------------
// Flash attention: bf16 mma + ldsm x4 + cp.async double-buffered K/V;
// mask direct-LDG from g_m2 into fragments. BM=128 (8 warps), BN=64.
// ---------------------------------------------------------------------------
#define BM    128
#define BN    64
#define BSTR  72

#define KOFF0 0
#define KOFF1 (BN*BSTR*2)          // 9216
#define VOFF0 (2*BN*BSTR*2)        // 18432
#define VOFF1 (3*BN*BSTR*2)        // 27648
#define POFF  (4*BN*BSTR*2)        // 36864
#define FLASH_SMEM (POFF + BM*BSTR*2)   // 55296

__global__ void __launch_bounds__(256, 2) flash_kernel()
{
    extern __shared__ char sm[];
    const uint32_t smb = smem_u32(sm);
    __nv_bfloat16* Ps  = (__nv_bfloat16*)(sm + POFF);

    const int tb  = blockIdx.x, bh = blockIdx.y;
    const int b   = bh >> 3;
    const int t0  = tb * BM;
    const int tid = threadIdx.x;
    const int w   = tid >> 5, lane = tid & 31;
    const int g   = lane >> 2, t = lane & 3;
    const int m0  = w * 16;
    const int rA  = m0 + g, rB = rA + 8;

    const __nv_bfloat16* qp = g_q + (size_t)bh * T_ * D_ + (size_t)t0 * D_;
    const __nv_bfloat16* kp = g_k + (size_t)bh * S_ * D_;
    const __nv_bfloat16* vp = g_v + (size_t)bh * S_ * D_;
    const uint32_t* m2 = g_m2 + (size_t)((b * 16 + tb) * 32) * 4096;

    // ---- stage Q into Ps region, hoist A-fragments
    for (int i = tid; i < BM * 8; i += 256) {
        int r = i >> 3, c8 = (i & 7) * 8;
        *(uint4*)(Ps + r * BSTR + c8) = *(const uint4*)(qp + (size_t)r * D_ + c8);
    }
    __syncthreads();
    uint32_t qf[4][4];
    {
        int row = m0 + (lane & 15);
        int ch  = (lane >> 4) * 8;
        #pragma unroll
        for (int kk = 0; kk < 4; kk++)
            ldsm_x4(qf[kk][0], qf[kk][1], qf[kk][2], qf[kk][3],
                    smb + (uint32_t)(POFF + (row * BSTR + kk * 16 + ch) * 2));
    }

    float O[8][4];
    #pragma unroll
    for (int i = 0; i < 8; i++)
        #pragma unroll
        for (int j = 0; j < 4; j++) O[i][j] = 0.0f;
    float mstA = -3.0e38f, mstB = -3.0e38f, lA = 0.0f, lB = 0.0f;

    // LDSM lane address components
    const int kq_row = ((lane >> 4) & 1) * 8 + (lane & 7);  // x4: matrix pair rows
    const int kq_ch  = ((lane >> 3) & 1) * 8;
    const int p_row  = m0 + (lane & 15);
    const int p_ch   = (lane >> 4) * 8;
    const int v_row  = lane & 15;
    const int v_c    = (lane >> 4) * 8;

    // cp.async staging: thread covers chunks tid and tid+256 of 512 (16B each)
    const int c0r = tid >> 3,        c0c = (tid & 7) * 8;
    const int c1r = (tid + 256) >> 3, c1c = (tid & 7) * 8;

    auto stageKV = [&](int s0, int bufi) {
        uint32_t kbase = smb + (bufi ? KOFF1 : KOFF0);
        uint32_t vbase = smb + (bufi ? VOFF1 : VOFF0);
        const __nv_bfloat16* ks = kp + (size_t)s0 * D_;
        const __nv_bfloat16* vs = vp + (size_t)s0 * D_;
        cp16(kbase + (uint32_t)(c0r * BSTR + c0c) * 2, ks + (size_t)c0r * D_ + c0c);
        cp16(kbase + (uint32_t)(c1r * BSTR + c1c) * 2, ks + (size_t)c1r * D_ + c1c);
        cp16(vbase + (uint32_t)(c0r * BSTR + c0c) * 2, vs + (size_t)c0r * D_ + c0c);
        cp16(vbase + (uint32_t)(c1r * BSTR + c1c) * 2, vs + (size_t)c1r * D_ + c1c);
    };

    stageKV(0, 0);
    CP_COMMIT;
    int cur = 0;

    for (int it = 0; it < S_ / BN; it++) {
        CP_WAIT0;
        __syncthreads();
        if (it + 1 < S_ / BN) { stageKV((it + 1) * BN, cur ^ 1); CP_COMMIT; }

        const uint32_t kcur = smb + (cur ? KOFF1 : KOFF0);
        const uint32_t vcur = smb + (cur ? VOFF1 : VOFF0);

        // ---- QK^T
        float sc[8][4];
        #pragma unroll
        for (int i = 0; i < 8; i++)
            #pragma unroll
            for (int j = 0; j < 4; j++) sc[i][j] = 0.0f;

        #pragma unroll
        for (int kk = 0; kk < 4; kk++) {
            #pragma unroll
            for (int ntp = 0; ntp < 4; ntp++) {
                uint32_t b0, b1f, b2f, b3f;
                ldsm_x4(b0, b1f, b2f, b3f,
                        kcur + (uint32_t)(((ntp * 16 + kq_row) * BSTR + kk * 16 + kq_ch) * 2));
                mma_bf16(sc[2 * ntp],     qf[kk][0], qf[kk][1], qf[kk][2], qf[kk][3], b0,  b1f);
                mma_bf16(sc[2 * ntp + 1], qf[kk][0], qf[kk][1], qf[kk][2], qf[kk][3], b2f, b3f);
            }
        }

        // ---- mask (direct fragment LDG) + online softmax (base 2)
        const uint32_t* mt_ = m2 + (size_t)it * 4096;
        float mxA = -3.0e38f, mxB = -3.0e38f;
        #pragma unroll
        for (int nt = 0; nt < 8; nt++) {
            uint32_t wa = mt_[nt * 512 + rA * 4 + t];
            uint32_t wb = mt_[nt * 512 + rB * 4 + t];
            sc[nt][0] += __uint_as_float(wa << 16);
            sc[nt][1] += __uint_as_float(wa & 0xffff0000u);
            sc[nt][2] += __uint_as_float(wb << 16);
            sc[nt][3] += __uint_as_float(wb & 0xffff0000u);
            mxA = fmaxf(mxA, fmaxf(sc[nt][0], sc[nt][1]));
            mxB = fmaxf(mxB, fmaxf(sc[nt][2], sc[nt][3]));
        }
        mxA = fmaxf(mxA, __shfl_xor_sync(0xffffffffu, mxA, 1));
        mxA = fmaxf(mxA, __shfl_xor_sync(0xffffffffu, mxA, 2));
        mxB = fmaxf(mxB, __shfl_xor_sync(0xffffffffu, mxB, 1));
        mxB = fmaxf(mxB, __shfl_xor_sync(0xffffffffu, mxB, 2));

        float nmA = fmaxf(mstA, mxA), nmB = fmaxf(mstB, mxB);
        float aA = ex2(mstA - nmA), aB = ex2(mstB - nmB);
        mstA = nmA; mstB = nmB;

        float sA = 0.0f, sB = 0.0f;
        #pragma unroll
        for (int nt = 0; nt < 8; nt++) {
            float p0 = ex2(sc[nt][0] - nmA);
            float p1 = ex2(sc[nt][1] - nmA);
            float p2 = ex2(sc[nt][2] - nmB);
            float p3 = ex2(sc[nt][3] - nmB);
            sA += p0 + p1; sB += p2 + p3;
            *(uint32_t*)(Ps + rA * BSTR + nt * 8 + 2 * t) = bf16x2(p0, p1);
            *(uint32_t*)(Ps + rB * BSTR + nt * 8 + 2 * t) = bf16x2(p2, p3);
        }
        sA += __shfl_xor_sync(0xffffffffu, sA, 1);
        sA += __shfl_xor_sync(0xffffffffu, sA, 2);
        sB += __shfl_xor_sync(0xffffffffu, sB, 1);
        sB += __shfl_xor_sync(0xffffffffu, sB, 2);
        lA = lA * aA + sA;
        lB = lB * aB + sB;

        #pragma unroll
        for (int nt = 0; nt < 8; nt++) {
            O[nt][0] *= aA; O[nt][1] *= aA;
            O[nt][2] *= aB; O[nt][3] *= aB;
        }
        __syncwarp();   // P strip produced & consumed within this warp

        // ---- P V
        #pragma unroll
        for (int kk = 0; kk < 4; kk++) {
            uint32_t pa0, pa1, pa2, pa3;
            ldsm_x4(pa0, pa1, pa2, pa3,
                    smb + (uint32_t)(POFF + (p_row * BSTR + kk * 16 + p_ch) * 2));
            #pragma unroll
            for (int ntp = 0; ntp < 4; ntp++) {
                uint32_t b0, b1f, b2f, b3f;
                ldsm_x4t(b0, b1f, b2f, b3f,
                         vcur + (uint32_t)(((kk * 16 + v_row) * BSTR + ntp * 16 + v_c) * 2));
                mma_bf16(O[2 * ntp],     pa0, pa1, pa2, pa3, b0,  b1f);
                mma_bf16(O[2 * ntp + 1], pa0, pa1, pa2, pa3, b2f, b3f);
            }
        }
        cur ^= 1;
    }

    // epilogue: normalize, scatter to ctx[(t*B+b)][h*64+c]
    const int h = bh & 7;
    float iA = 1.0f / lA, iB = 1.0f / lB;
    size_t rowA = (size_t)(t0 + rA) * B_ + b;
    size_t rowB = (size_t)(t0 + rB) * B_ + b;
    #pragma unroll
    for (int nt = 0; nt < 8; nt++) {
        *(float2*)(g_ctx + rowA * (H_ * D_) + h * D_ + nt * 8 + 2 * t) =
            make_float2(O[nt][0] * iA, O[nt][1] * iA);
        *(float2*)(g_ctx + rowB * (H_ * D_) + h * D_ + nt * 8 + 2 * t) =
            make_float2(O[nt][2] * iB, O[nt][3] * iB);
    }
}

// ---------------------------------------------------------------------------
// Output projection: out[8192,64] = ctx[8192,512] @ Wo[512,64] + bo (fp32)
// ---------------------------------------------------------------------------
__global__ void __launch_bounds__(256) outproj_kernel(
    const float* __restrict__ Wo, const float* __restrict__ bo,
    float* __restrict__ out)
{
    const int n0 = blockIdx.x * 32;
    const int j  = threadIdx.x & 63;
    const int rg = threadIdx.x >> 6;
    float acc[8];
    {
        float bv = bo[j];
        #pragma unroll
        for (int i = 0; i < 8; i++) acc[i] = bv;
    }
    for (int k = 0; k < 512; k += 4) {
        float w0 = Wo[(k + 0) * 64 + j];
        float w1 = Wo[(k + 1) * 64 + j];
        float w2 = Wo[(k + 2) * 64 + j];
        float w3 = Wo[(k + 3) * 64 + j];
        #pragma unroll
        for (int i = 0; i < 8; i++) {
            const float4 cv = *(const float4*)(g_ctx + (size_t)(n0 + rg * 8 + i) * 512 + k);
            acc[i] += cv.x * w0 + cv.y * w1 + cv.z * w2 + cv.w * w3;
        }
    }
    #pragma unroll
    for (int i = 0; i < 8; i++)
        out[(size_t)(n0 + rg * 8 + i) * 64 + j] = acc[i];
}

// ---------------------------------------------------------------------------
extern "C" void kernel_launch(void* const* d_in, const int* in_sizes, int n_in,
                              void* d_out, int out_size)
{
    const float* query = (const float*)d_in[0];
    const float* key   = (const float*)d_in[1];
    const float* value = (const float*)d_in[2];
    const float* mask  = (const float*)d_in[3];
    const float* Wq1 = (const float*)d_in[4];
    const float* bq1 = (const float*)d_in[5];
    const float* Wq2 = (const float*)d_in[6];
    const float* bq2 = (const float*)d_in[7];
    const float* Wk1 = (const float*)d_in[8];
    const float* bk1 = (const float*)d_in[9];
    const float* Wk2 = (const float*)d_in[10];
    const float* bk2 = (const float*)d_in[11];
    const float* Wv1 = (const float*)d_in[12];
    const float* bv1 = (const float*)d_in[13];
    const float* Wv2 = (const float*)d_in[14];
    const float* bv2 = (const float*)d_in[15];
    const float* Wo  = (const float*)d_in[16];
    const float* bo  = (const float*)d_in[17];
    float* out = (float*)d_out;

    mask_prep_kernel<<<B_ * 16 * 32, 256>>>(mask);

    dim3 mlpGrid(NROW_ / 32, 3);
    mlp_mma_kernel<<<mlpGrid, 256>>>(query, key, value,
                                     Wq1, bq1, Wq2, bq2,
                                     Wk1, bk1, Wk2, bk2,
                                     Wv1, bv1, Wv2, bv2);

    cudaFuncSetAttribute(flash_kernel,
                         cudaFuncAttributeMaxDynamicSharedMemorySize, FLASH_SMEM);
    dim3 fGrid(T_ / BM, B_ * H_);
    flash_kernel<<<fGrid, 256, FLASH_SMEM>>>();

    outproj_kernel<<<NROW_ / 32, 256>>>(Wo, bo, out);
}

// round 6
// speedup vs baseline: 4.7016x; 1.1947x over previous
#include <cuda_runtime.h>
#include <cuda_bf16.h>
#include <math.h>
#include <stdint.h>

#define H_    8
#define D_    64
#define HID_  256
#define T_    2048
#define S_    2048
#define B_    4
#define NROW_ (T_*B_)
#define LOG2E 1.44269504f

// Scratch (allocation-free)
__device__ __nv_bfloat16 g_q[B_*H_*T_*D_];
__device__ __nv_bfloat16 g_k[B_*H_*S_*D_];
__device__ __nv_bfloat16 g_v[B_*H_*S_*D_];
__device__ float g_ctx[NROW_*H_*D_];
// mask, bf16x2-packed in fragment-direct layout:
// [b*512 + tb*32 + sb][nt(8)][row(128)][t(4)] as uint32 (lo=col 2t, hi=col 2t+1)
__device__ uint32_t g_m2[(size_t)B_*16*32*4096];

__device__ __forceinline__ uint32_t smem_u32(const void* p) {
    return (uint32_t)__cvta_generic_to_shared(p);
}
__device__ __forceinline__ float to_tf32(float x) {
    float r; asm("cvt.rna.tf32.f32 %0, %1;" : "=f"(r) : "f"(x)); return r;
}
__device__ __forceinline__ uint32_t fu(float x) { return __float_as_uint(x); }
__device__ __forceinline__ float ex2(float x) {
    float r; asm("ex2.approx.ftz.f32 %0, %1;" : "=f"(r) : "f"(x)); return r;
}
__device__ __forceinline__ void ldsm_x4(uint32_t& r0, uint32_t& r1,
                                        uint32_t& r2, uint32_t& r3, uint32_t a) {
    asm volatile("ldmatrix.sync.aligned.m8n8.x4.shared.b16 {%0,%1,%2,%3}, [%4];"
                 : "=r"(r0), "=r"(r1), "=r"(r2), "=r"(r3) : "r"(a));
}
__device__ __forceinline__ void ldsm_x4t(uint32_t& r0, uint32_t& r1,
                                         uint32_t& r2, uint32_t& r3, uint32_t a) {
    asm volatile("ldmatrix.sync.aligned.m8n8.x4.trans.shared.b16 {%0,%1,%2,%3}, [%4];"
                 : "=r"(r0), "=r"(r1), "=r"(r2), "=r"(r3) : "r"(a));
}
__device__ __forceinline__ void mma_bf16(float* d,
    uint32_t a0, uint32_t a1, uint32_t a2, uint32_t a3, uint32_t b0, uint32_t b1)
{
    asm volatile(
        "mma.sync.aligned.m16n8k16.row.col.f32.bf16.bf16.f32 "
        "{%0,%1,%2,%3}, {%4,%5,%6,%7}, {%8,%9}, {%0,%1,%2,%3};"
        : "+f"(d[0]), "+f"(d[1]), "+f"(d[2]), "+f"(d[3])
        : "r"(a0), "r"(a1), "r"(a2), "r"(a3), "r"(b0), "r"(b1));
}
__device__ __forceinline__ void mma_tf32(float* d,
    uint32_t a0, uint32_t a1, uint32_t a2, uint32_t a3, uint32_t b0, uint32_t b1)
{
    asm volatile(
        "mma.sync.aligned.m16n8k8.row.col.f32.tf32.tf32.f32 "
        "{%0,%1,%2,%3}, {%4,%5,%6,%7}, {%8,%9}, {%0,%1,%2,%3};"
        : "+f"(d[0]), "+f"(d[1]), "+f"(d[2]), "+f"(d[3])
        : "r"(a0), "r"(a1), "r"(a2), "r"(a3), "r"(b0), "r"(b1));
}
__device__ __forceinline__ uint32_t bf16x2(float lo, float hi) {
    uint32_t r;
    asm("cvt.rn.bf16x2.f32 %0, %1, %2;" : "=r"(r) : "f"(hi), "f"(lo));
    return r;
}
__device__ __forceinline__ void cp16(uint32_t dst, const void* src) {
    asm volatile("cp.async.cg.shared.global [%0], [%1], 16;"
                 :: "r"(dst), "l"(src));
}
#define CP_COMMIT asm volatile("cp.async.commit_group;")
#define CP_WAIT0  asm volatile("cp.async.wait_group 0;")

// ---------------------------------------------------------------------------
// Mask pre-pack: mask[b][t][s] fp32 -> bf16x2 * log2e in fragment layout.
// grid: B_*16*32 tiles (128x64 each), 256 threads.
// ---------------------------------------------------------------------------
__global__ void __launch_bounds__(256) mask_prep_kernel(const float* __restrict__ mask)
{
    const int tile = blockIdx.x;
    const int b  = tile >> 9;
    const int tb = (tile >> 5) & 15;
    const int sb = tile & 31;
    const float* mp = mask + (size_t)b * T_ * S_ + (size_t)(tb * 128) * S_ + sb * 64;
    uint32_t* op = g_m2 + (size_t)tile * 4096;
    const int tid = threadIdx.x;
    #pragma unroll
    for (int it = 0; it < 16; it++) {
        int idx = tid + it * 256;
        int r = idx >> 5, cp = idx & 31;
        float2 mv = *(const float2*)(mp + (size_t)r * S_ + cp * 2);
        op[(cp >> 2) * 512 + r * 4 + (cp & 3)] =
            bf16x2(mv.x * LOG2E, mv.y * LOG2E);
    }
}

// ---------------------------------------------------------------------------
// MLP via tf32 mma: block = 32 rows, 8 warps; layer1 n-split 8x32,
// layer2 n-split 8x64 (head h == warp id). grid (256, 3).
// ---------------------------------------------------------------------------
__global__ void __launch_bounds__(256) mlp_mma_kernel(
    const float* __restrict__ xq, const float* __restrict__ xk,
    const float* __restrict__ xv,
    const float* __restrict__ Wq1, const float* __restrict__ bq1,
    const float* __restrict__ Wq2, const float* __restrict__ bq2,
    const float* __restrict__ Wk1, const float* __restrict__ bk1,
    const float* __restrict__ Wk2, const float* __restrict__ bk2,
    const float* __restrict__ Wv1, const float* __restrict__ bv1,
    const float* __restrict__ Wv2, const float* __restrict__ bv2)
{
    const int which = blockIdx.y;
    const float *x, *W1, *b1v, *W2, *b2v;
    __nv_bfloat16* outp;
    float scale;
    if (which == 0) { x=xq; W1=Wq1; b1v=bq1; W2=Wq2; b2v=bq2; outp=g_q; scale=0.125f*LOG2E; }
    else if (which == 1) { x=xk; W1=Wk1; b1v=bk1; W2=Wk2; b2v=bk2; outp=g_k; scale=1.0f; }
    else { x=xv; W1=Wv1; b1v=bv1; W2=Wv2; b2v=bv2; outp=g_v; scale=1.0f; }

    __shared__ float Xs[32][68];
    __shared__ float Hs[32][260];

    const int n0r = blockIdx.x * 32;
    const int tid = threadIdx.x;
    const int w = tid >> 5, lane = tid & 31;
    const int g = lane >> 2, t = lane & 3;

    // load X tile [32][64] (tf32-rounded)
    for (int i = tid; i < 32 * 16; i += 256) {
        int r = i >> 4, c4 = (i & 15) * 4;
        float4 v = *(const float4*)(x + (size_t)(n0r + r) * 64 + c4);
        v.x = to_tf32(v.x); v.y = to_tf32(v.y);
        v.z = to_tf32(v.z); v.w = to_tf32(v.w);
        *(float4*)&Xs[r][c4] = v;
    }
    __syncthreads();

    // ---- layer 1: H = relu(X @ W1 + b1); warp covers cols [w*32, w*32+32)
    {
        float acc[2][4][4];
        #pragma unroll
        for (int mt = 0; mt < 2; mt++)
            #pragma unroll
            for (int nt = 0; nt < 4; nt++)
                #pragma unroll
                for (int j = 0; j < 4; j++) acc[mt][nt][j] = 0.0f;

        const int n0 = w * 32;
        #pragma unroll
        for (int k0 = 0; k0 < 64; k0 += 8) {
            uint32_t a[2][4];
            #pragma unroll
            for (int mt = 0; mt < 2; mt++) {
                int rA_ = mt * 16 + g;
                a[mt][0] = fu(Xs[rA_][k0 + t]);
                a[mt][1] = fu(Xs[rA_ + 8][k0 + t]);
                a[mt][2] = fu(Xs[rA_][k0 + t + 4]);
                a[mt][3] = fu(Xs[rA_ + 8][k0 + t + 4]);
            }
            #pragma unroll
            for (int nt = 0; nt < 4; nt++) {
                int n = n0 + nt * 8 + g;
                uint32_t b0 = fu(to_tf32(W1[(k0 + t) * HID_ + n]));
                uint32_t b1f = fu(to_tf32(W1[(k0 + t + 4) * HID_ + n]));
                mma_tf32(acc[0][nt], a[0][0], a[0][1], a[0][2], a[0][3], b0, b1f);
                mma_tf32(acc[1][nt], a[1][0], a[1][1], a[1][2], a[1][3], b0, b1f);
            }
        }
        // bias + relu -> Hs (tf32-rounded)
        #pragma unroll
        for (int nt = 0; nt < 4; nt++) {
            int j = n0 + nt * 8 + 2 * t;
            float bz0 = b1v[j], bz1 = b1v[j + 1];
            #pragma unroll
            for (int mt = 0; mt < 2; mt++) {
                int rA_ = mt * 16 + g;
                float2 v0 = make_float2(
                    to_tf32(fmaxf(acc[mt][nt][0] + bz0, 0.0f)),
                    to_tf32(fmaxf(acc[mt][nt][1] + bz1, 0.0f)));
                float2 v1 = make_float2(
                    to_tf32(fmaxf(acc[mt][nt][2] + bz0, 0.0f)),
                    to_tf32(fmaxf(acc[mt][nt][3] + bz1, 0.0f)));
                *(float2*)&Hs[rA_][j] = v0;
                *(float2*)&Hs[rA_ + 8][j] = v1;
            }
        }
    }
    __syncthreads();

    // ---- layer 2: Y = H @ W2 + b2; warp covers cols [w*64, w*64+64) -> head w
    {
        float acc[2][8][4];
        #pragma unroll
        for (int mt = 0; mt < 2; mt++)
            #pragma unroll
            for (int nt = 0; nt < 8; nt++)
                #pragma unroll
                for (int j = 0; j < 4; j++) acc[mt][nt][j] = 0.0f;

        const int n0 = w * 64;
        #pragma unroll 4
        for (int k0 = 0; k0 < HID_; k0 += 8) {
            uint32_t a[2][4];
            #pragma unroll
            for (int mt = 0; mt < 2; mt++) {
                int rA_ = mt * 16 + g;
                a[mt][0] = fu(Hs[rA_][k0 + t]);
                a[mt][1] = fu(Hs[rA_ + 8][k0 + t]);
                a[mt][2] = fu(Hs[rA_][k0 + t + 4]);
                a[mt][3] = fu(Hs[rA_ + 8][k0 + t + 4]);
            }
            #pragma unroll
            for (int nt = 0; nt < 8; nt++) {
                int n = n0 + nt * 8 + g;
                uint32_t b0 = fu(to_tf32(W2[(k0 + t) * 512 + n]));
                uint32_t b1f = fu(to_tf32(W2[(k0 + t + 4) * 512 + n]));
                mma_tf32(acc[0][nt], a[0][0], a[0][1], a[0][2], a[0][3], b0, b1f);
                mma_tf32(acc[1][nt], a[1][0], a[1][1], a[1][2], a[1][3], b0, b1f);
            }
        }
        // epilogue: bias, scale, bf16x2 scatter to [(b*H+w)*T + tt][d]
        #pragma unroll
        for (int nt = 0; nt < 8; nt++) {
            int d = nt * 8 + 2 * t;
            float bz0 = b2v[n0 + d], bz1 = b2v[n0 + d + 1];
            #pragma unroll
            for (int mt = 0; mt < 2; mt++) {
                #pragma unroll
                for (int half = 0; half < 2; half++) {
                    int nrow = n0r + mt * 16 + g + half * 8;
                    int tt = nrow >> 2, bb = nrow & 3;
                    float v0 = (acc[mt][nt][half * 2 + 0] + bz0) * scale;
                    float v1 = (acc[mt][nt][half * 2 + 1] + bz1) * scale;
                    *(uint32_t*)(outp + ((size_t)(bb * H_ + w) * T_ + tt) * D_ + d) =
                        bf16x2(v0, v1);
                }
            }
        }
    }
}

// ---------------------------------------------------------------------------
// Flash attention: bf16 mma + ldsm x4 + cp.async double-buffered K/V;
// mask direct-LDG from g_m2 into fragments. BM=128 (8 warps), BN=64.
// ---------------------------------------------------------------------------
#define BM    128
#define BN    64
#define BSTR  72

#define KOFF0 0
#define KOFF1 (BN*BSTR*2)          // 9216
#define VOFF0 (2*BN*BSTR*2)        // 18432
#define VOFF1 (3*BN*BSTR*2)        // 27648
#define POFF  (4*BN*BSTR*2)        // 36864
#define FLASH_SMEM (POFF + BM*BSTR*2)   // 55296

__global__ void __launch_bounds__(256, 2) flash_kernel()
{
    extern __shared__ char sm[];
    const uint32_t smb = smem_u32(sm);
    __nv_bfloat16* Ps  = (__nv_bfloat16*)(sm + POFF);

    const int tb  = blockIdx.x, bh = blockIdx.y;
    const int b   = bh >> 3;
    const int t0  = tb * BM;
    const int tid = threadIdx.x;
    const int w   = tid >> 5, lane = tid & 31;
    const int g   = lane >> 2, t = lane & 3;
    const int m0  = w * 16;
    const int rA  = m0 + g, rB = rA + 8;

    const __nv_bfloat16* qp = g_q + (size_t)bh * T_ * D_ + (size_t)t0 * D_;
    const __nv_bfloat16* kp = g_k + (size_t)bh * S_ * D_;
    const __nv_bfloat16* vp = g_v + (size_t)bh * S_ * D_;
    const uint32_t* m2 = g_m2 + (size_t)((b * 16 + tb) * 32) * 4096;

    // ---- stage Q into Ps region, hoist A-fragments
    for (int i = tid; i < BM * 8; i += 256) {
        int r = i >> 3, c8 = (i & 7) * 8;
        *(uint4*)(Ps + r * BSTR + c8) = *(const uint4*)(qp + (size_t)r * D_ + c8);
    }
    __syncthreads();
    uint32_t qf[4][4];
    {
        int row = m0 + (lane & 15);
        int ch  = (lane >> 4) * 8;
        #pragma unroll
        for (int kk = 0; kk < 4; kk++)
            ldsm_x4(qf[kk][0], qf[kk][1], qf[kk][2], qf[kk][3],
                    smb + (uint32_t)(POFF + (row * BSTR + kk * 16 + ch) * 2));
    }

    float O[8][4];
    #pragma unroll
    for (int i = 0; i < 8; i++)
        #pragma unroll
        for (int j = 0; j < 4; j++) O[i][j] = 0.0f;
    float mstA = -3.0e38f, mstB = -3.0e38f, lA = 0.0f, lB = 0.0f;

    // LDSM lane address components
    const int kq_row = ((lane >> 4) & 1) * 8 + (lane & 7);  // x4: matrix pair rows
    const int kq_ch  = ((lane >> 3) & 1) * 8;
    const int p_row  = m0 + (lane & 15);
    const int p_ch   = (lane >> 4) * 8;
    const int v_row  = lane & 15;
    const int v_c    = (lane >> 4) * 8;

    // cp.async staging: thread covers chunks tid and tid+256 of 512 (16B each)
    const int c0r = tid >> 3,        c0c = (tid & 7) * 8;
    const int c1r = (tid + 256) >> 3, c1c = (tid & 7) * 8;

    auto stageKV = [&](int s0, int bufi) {
        uint32_t kbase = smb + (bufi ? KOFF1 : KOFF0);
        uint32_t vbase = smb + (bufi ? VOFF1 : VOFF0);
        const __nv_bfloat16* ks = kp + (size_t)s0 * D_;
        const __nv_bfloat16* vs = vp + (size_t)s0 * D_;
        cp16(kbase + (uint32_t)(c0r * BSTR + c0c) * 2, ks + (size_t)c0r * D_ + c0c);
        cp16(kbase + (uint32_t)(c1r * BSTR + c1c) * 2, ks + (size_t)c1r * D_ + c1c);
        cp16(vbase + (uint32_t)(c0r * BSTR + c0c) * 2, vs + (size_t)c0r * D_ + c0c);
        cp16(vbase + (uint32_t)(c1r * BSTR + c1c) * 2, vs + (size_t)c1r * D_ + c1c);
    };

    stageKV(0, 0);
    CP_COMMIT;
    int cur = 0;

    for (int it = 0; it < S_ / BN; it++) {
        CP_WAIT0;
        __syncthreads();
        if (it + 1 < S_ / BN) { stageKV((it + 1) * BN, cur ^ 1); CP_COMMIT; }

        const uint32_t kcur = smb + (cur ? KOFF1 : KOFF0);
        const uint32_t vcur = smb + (cur ? VOFF1 : VOFF0);

        // ---- QK^T
        float sc[8][4];
        #pragma unroll
        for (int i = 0; i < 8; i++)
            #pragma unroll
            for (int j = 0; j < 4; j++) sc[i][j] = 0.0f;

        #pragma unroll
        for (int kk = 0; kk < 4; kk++) {
            #pragma unroll
            for (int ntp = 0; ntp < 4; ntp++) {
                uint32_t b0, b1f, b2f, b3f;
                ldsm_x4(b0, b1f, b2f, b3f,
                        kcur + (uint32_t)(((ntp * 16 + kq_row) * BSTR + kk * 16 + kq_ch) * 2));
                mma_bf16(sc[2 * ntp],     qf[kk][0], qf[kk][1], qf[kk][2], qf[kk][3], b0,  b1f);
                mma_bf16(sc[2 * ntp + 1], qf[kk][0], qf[kk][1], qf[kk][2], qf[kk][3], b2f, b3f);
            }
        }

        // ---- mask (direct fragment LDG) + online softmax (base 2)
        const uint32_t* mt_ = m2 + (size_t)it * 4096;
        float mxA = -3.0e38f, mxB = -3.0e38f;
        #pragma unroll
        for (int nt = 0; nt < 8; nt++) {
            uint32_t wa = mt_[nt * 512 + rA * 4 + t];
            uint32_t wb = mt_[nt * 512 + rB * 4 + t];
            sc[nt][0] += __uint_as_float(wa << 16);
            sc[nt][1] += __uint_as_float(wa & 0xffff0000u);
            sc[nt][2] += __uint_as_float(wb << 16);
            sc[nt][3] += __uint_as_float(wb & 0xffff0000u);
            mxA = fmaxf(mxA, fmaxf(sc[nt][0], sc[nt][1]));
            mxB = fmaxf(mxB, fmaxf(sc[nt][2], sc[nt][3]));
        }
        mxA = fmaxf(mxA, __shfl_xor_sync(0xffffffffu, mxA, 1));
        mxA = fmaxf(mxA, __shfl_xor_sync(0xffffffffu, mxA, 2));
        mxB = fmaxf(mxB, __shfl_xor_sync(0xffffffffu, mxB, 1));
        mxB = fmaxf(mxB, __shfl_xor_sync(0xffffffffu, mxB, 2));

        float nmA = fmaxf(mstA, mxA), nmB = fmaxf(mstB, mxB);
        float aA = ex2(mstA - nmA), aB = ex2(mstB - nmB);
        mstA = nmA; mstB = nmB;

        float sA = 0.0f, sB = 0.0f;
        #pragma unroll
        for (int nt = 0; nt < 8; nt++) {
            float p0 = ex2(sc[nt][0] - nmA);
            float p1 = ex2(sc[nt][1] - nmA);
            float p2 = ex2(sc[nt][2] - nmB);
            float p3 = ex2(sc[nt][3] - nmB);
            sA += p0 + p1; sB += p2 + p3;
            *(uint32_t*)(Ps + rA * BSTR + nt * 8 + 2 * t) = bf16x2(p0, p1);
            *(uint32_t*)(Ps + rB * BSTR + nt * 8 + 2 * t) = bf16x2(p2, p3);
        }
        sA += __shfl_xor_sync(0xffffffffu, sA, 1);
        sA += __shfl_xor_sync(0xffffffffu, sA, 2);
        sB += __shfl_xor_sync(0xffffffffu, sB, 1);
        sB += __shfl_xor_sync(0xffffffffu, sB, 2);
        lA = lA * aA + sA;
        lB = lB * aB + sB;

        #pragma unroll
        for (int nt = 0; nt < 8; nt++) {
            O[nt][0] *= aA; O[nt][1] *= aA;
            O[nt][2] *= aB; O[nt][3] *= aB;
        }
        __syncwarp();   // P strip produced & consumed within this warp

        // ---- P V
        #pragma unroll
        for (int kk = 0; kk < 4; kk++) {
            uint32_t pa0, pa1, pa2, pa3;
            ldsm_x4(pa0, pa1, pa2, pa3,
                    smb + (uint32_t)(POFF + (p_row * BSTR + kk * 16 + p_ch) * 2));
            #pragma unroll
            for (int ntp = 0; ntp < 4; ntp++) {
                uint32_t b0, b1f, b2f, b3f;
                ldsm_x4t(b0, b1f, b2f, b3f,
                         vcur + (uint32_t)(((kk * 16 + v_row) * BSTR + ntp * 16 + v_c) * 2));
                mma_bf16(O[2 * ntp],     pa0, pa1, pa2, pa3, b0,  b1f);
                mma_bf16(O[2 * ntp + 1], pa0, pa1, pa2, pa3, b2f, b3f);
            }
        }
        cur ^= 1;
    }

    // epilogue: normalize, scatter to ctx[(t*B+b)][h*64+c]
    const int h = bh & 7;
    float iA = 1.0f / lA, iB = 1.0f / lB;
    size_t rowA = (size_t)(t0 + rA) * B_ + b;
    size_t rowB = (size_t)(t0 + rB) * B_ + b;
    #pragma unroll
    for (int nt = 0; nt < 8; nt++) {
        *(float2*)(g_ctx + rowA * (H_ * D_) + h * D_ + nt * 8 + 2 * t) =
            make_float2(O[nt][0] * iA, O[nt][1] * iA);
        *(float2*)(g_ctx + rowB * (H_ * D_) + h * D_ + nt * 8 + 2 * t) =
            make_float2(O[nt][2] * iB, O[nt][3] * iB);
    }
}

// ---------------------------------------------------------------------------
// Output projection via tf32 mma with 4-way K-split.
// block = 32 rows (2 m16 strips) x 8 warps (2 m x 4 k-chunks of 128).
// ctx tile staged tf32-rounded in smem (stride 516 == 4 mod 32, conflict-free
// fragment LDS); Wo B-fragments via direct LDG (L2-hot, HW tf32-truncated).
// K-split partials reduced in smem with fixed order (deterministic).
// ---------------------------------------------------------------------------
#define CSTR  516
#define PSTR  66
#define OUT_CS_FLOATS  (32 * CSTR)              // 16512
#define OUT_PR_FLOATS  (128 * PSTR)             // 8448 (4 ksplits x 32 rows)
#define OUT_SMEM ((OUT_CS_FLOATS + OUT_PR_FLOATS) * 4)   // 99840 B

__global__ void __launch_bounds__(256) outproj_kernel(
    const float* __restrict__ Wo, const float* __restrict__ bo,
    float* __restrict__ out)
{
    extern __shared__ float osm[];
    float* Cs = osm;                    // [32][CSTR] tf32 ctx tile
    float* Pr = osm + OUT_CS_FLOATS;    // [4][32][PSTR] k-split partials

    const int n0  = blockIdx.x * 32;
    const int tid = threadIdx.x;
    const int w   = tid >> 5, lane = tid & 31;
    const int g   = lane >> 2, t = lane & 3;
    const int mw  = w & 1;              // m16 strip
    const int kw  = w >> 1;             // k chunk (128 wide)
    const int rA  = mw * 16 + g, rB = rA + 8;

    // stage ctx [32][512] -> Cs (tf32-rounded), coalesced float4
    for (int i = tid; i < 32 * 128; i += 256) {
        int r = i >> 7, c4 = (i & 127) * 4;
        float4 v = *(const float4*)(g_ctx + (size_t)(n0 + r) * 512 + c4);
        v.x = to_tf32(v.x); v.y = to_tf32(v.y);
        v.z = to_tf32(v.z); v.w = to_tf32(v.w);
        *(float4*)&Cs[r * CSTR + c4] = v;
    }
    __syncthreads();

    float acc[8][4];
    #pragma unroll
    for (int nt = 0; nt < 8; nt++)
        #pragma unroll
        for (int j = 0; j < 4; j++) acc[nt][j] = 0.0f;

    #pragma unroll 4
    for (int step = 0; step < 16; step++) {
        const int k0 = kw * 128 + step * 8;
        uint32_t a0 = fu(Cs[rA * CSTR + k0 + t]);
        uint32_t a1 = fu(Cs[rB * CSTR + k0 + t]);
        uint32_t a2 = fu(Cs[rA * CSTR + k0 + t + 4]);
        uint32_t a3 = fu(Cs[rB * CSTR + k0 + t + 4]);
        #pragma unroll
        for (int nt = 0; nt < 8; nt++) {
            int n = nt * 8 + g;
            uint32_t b0  = fu(Wo[(k0 + t) * 64 + n]);
            uint32_t b1f = fu(Wo[(k0 + t + 4) * 64 + n]);
            mma_tf32(acc[nt], a0, a1, a2, a3, b0, b1f);
        }
    }

    // store k-split partials
    #pragma unroll
    for (int nt = 0; nt < 8; nt++) {
        int c = nt * 8 + 2 * t;
        *(float2*)&Pr[(kw * 32 + rA) * PSTR + c] = make_float2(acc[nt][0], acc[nt][1]);
        *(float2*)&Pr[(kw * 32 + rB) * PSTR + c] = make_float2(acc[nt][2], acc[nt][3]);
    }
    __syncthreads();

    // reduce 4 partials + bias, write out (each thread: row tid>>3, 8 cols)
    {
        int r  = tid >> 3;
        int c0 = (tid & 7) * 8;
        float res[8];
        #pragma unroll
        for (int j = 0; j < 8; j++) {
            int c = c0 + j;
            res[j] = Pr[(0 * 32 + r) * PSTR + c]
                   + Pr[(1 * 32 + r) * PSTR + c]
                   + Pr[(2 * 32 + r) * PSTR + c]
                   + Pr[(3 * 32 + r) * PSTR + c]
                   + bo[c];
        }
        float* op = out + (size_t)(n0 + r) * 64 + c0;
        *(float4*)(op)     = make_float4(res[0], res[1], res[2], res[3]);
        *(float4*)(op + 4) = make_float4(res[4], res[5], res[6], res[7]);
    }
}

// ---------------------------------------------------------------------------
extern "C" void kernel_launch(void* const* d_in, const int* in_sizes, int n_in,
                              void* d_out, int out_size)
{
    const float* query = (const float*)d_in[0];
    const float* key   = (const float*)d_in[1];
    const float* value = (const float*)d_in[2];
    const float* mask  = (const float*)d_in[3];
    const float* Wq1 = (const float*)d_in[4];
    const float* bq1 = (const float*)d_in[5];
    const float* Wq2 = (const float*)d_in[6];
    const float* bq2 = (const float*)d_in[7];
    const float* Wk1 = (const float*)d_in[8];
    const float* bk1 = (const float*)d_in[9];
    const float* Wk2 = (const float*)d_in[10];
    const float* bk2 = (const float*)d_in[11];
    const float* Wv1 = (const float*)d_in[12];
    const float* bv1 = (const float*)d_in[13];
    const float* Wv2 = (const float*)d_in[14];
    const float* bv2 = (const float*)d_in[15];
    const float* Wo  = (const float*)d_in[16];
    const float* bo  = (const float*)d_in[17];
    float* out = (float*)d_out;

    mask_prep_kernel<<<B_ * 16 * 32, 256>>>(mask);

    dim3 mlpGrid(NROW_ / 32, 3);
    mlp_mma_kernel<<<mlpGrid, 256>>>(query, key, value,
                                     Wq1, bq1, Wq2, bq2,
                                     Wk1, bk1, Wk2, bk2,
                                     Wv1, bv1, Wv2, bv2);

    cudaFuncSetAttribute(flash_kernel,
                         cudaFuncAttributeMaxDynamicSharedMemorySize, FLASH_SMEM);
    dim3 fGrid(T_ / BM, B_ * H_);
    flash_kernel<<<fGrid, 256, FLASH_SMEM>>>();

    cudaFuncSetAttribute(outproj_kernel,
                         cudaFuncAttributeMaxDynamicSharedMemorySize, OUT_SMEM);
    outproj_kernel<<<NROW_ / 32, 256, OUT_SMEM>>>(Wo, bo, out);
}